// round 2
// baseline (speedup 1.0000x reference)
#include <cuda_runtime.h>
#include <cuda_bf16.h>

#define NN 50000
#define EE 800000
#define FDIM 256     // IN == HID*HEADS == 256
#define HEADS 4
#define HID 64

// ---------------- scratch (static device globals; allocation-free) ----------------
__device__ float  d_xn[NN * FDIM];     // normalized features (reused for layer 2)
__device__ float  d_y1[NN * FDIM];     // linear output / accumulation target / x1
__device__ float  d_h1[NN * FDIM];     // GAT1 transformed features
__device__ float4 d_als1[NN];
__device__ float4 d_ald1[NN];
__device__ float4 d_denom1[NN];
__device__ float4 d_ex1[EE];
__device__ float2 d_h3[NN];
__device__ float  d_als3[NN];
__device__ float  d_ald3[NN];
__device__ float  d_denom3[NN];
__device__ float  d_ex3[EE];
__device__ float  d_bnsum[FDIM];
__device__ float  d_bnsumsq[FDIM];
__device__ float  d_scale[FDIM];
__device__ float  d_shift[FDIM];

__device__ __forceinline__ float lrelu(float x) { return x > 0.f ? x : 0.2f * x; }

// ---------------- zeroing ----------------
__global__ void zero_bn() {
    d_bnsum[threadIdx.x] = 0.f;
    d_bnsumsq[threadIdx.x] = 0.f;
}

__global__ void zero_denoms() {
    int i = blockIdx.x * blockDim.x + threadIdx.x;
    if (i < NN * 4) ((float*)d_denom1)[i] = 0.f;
    if (i < NN) d_denom3[i] = 0.f;
}

// ---------------- batchnorm ----------------
__global__ void bn_stats(const float* __restrict__ x) {
    int c = threadIdx.x;
    float s = 0.f, s2 = 0.f;
    for (int r = blockIdx.x; r < NN; r += gridDim.x) {
        float v = x[r * FDIM + c];
        s += v; s2 += v * v;
    }
    atomicAdd(&d_bnsum[c], s);
    atomicAdd(&d_bnsumsq[c], s2);
}

__global__ void bn_finalize(const float* __restrict__ g, const float* __restrict__ b) {
    int c = threadIdx.x;
    const float invn = 1.0f / (float)NN;
    float mu = d_bnsum[c] * invn;
    float var = d_bnsumsq[c] * invn - mu * mu;
    float rs = rsqrtf(var + 1e-5f);
    float sc = rs * g[c];
    d_scale[c] = sc;
    d_shift[c] = b[c] - mu * sc;
}

__global__ void bn_apply(const float* __restrict__ x, float* __restrict__ xo) {
    int i = blockIdx.x * blockDim.x + threadIdx.x;
    if (i < NN * FDIM) {
        int c = i & (FDIM - 1);
        xo[i] = x[i] * d_scale[c] + d_shift[c];
    }
}

// ---------------- GEMM: C[M,256] = A[M,256] @ B[256,256] (+ bias1 + bias2) ----------------
// 64x64 tile, TK=16, 256 threads, 4x4 micro-tile per thread
__global__ void gemm256(const float* __restrict__ A, const float* __restrict__ B,
                        const float* __restrict__ bias1, const float* __restrict__ bias2,
                        float* __restrict__ C) {
    __shared__ float sA[16][65];
    __shared__ float sB[16][64];
    int t = threadIdx.x;
    int tx = t & 15, ty = t >> 4;
    int m0 = blockIdx.x * 64, n0 = blockIdx.y * 64;
    float acc[4][4] = {};

    for (int k0 = 0; k0 < 256; k0 += 16) {
        // load A tile (coalesced along k within a row)
        #pragma unroll
        for (int j = 0; j < 4; j++) {
            int i = t + j * 256;
            int k = i & 15, m = i >> 4;
            int gm = m0 + m;
            sA[k][m] = (gm < NN) ? A[gm * 256 + k0 + k] : 0.f;
        }
        // load B tile (coalesced along n)
        #pragma unroll
        for (int j = 0; j < 4; j++) {
            int i = t + j * 256;
            int n = i & 63, k = i >> 6;
            sB[k][n] = B[(k0 + k) * 256 + n0 + n];
        }
        __syncthreads();
        #pragma unroll
        for (int kk = 0; kk < 16; kk++) {
            float a[4], b[4];
            #pragma unroll
            for (int i = 0; i < 4; i++) a[i] = sA[kk][ty * 4 + i];
            #pragma unroll
            for (int j = 0; j < 4; j++) b[j] = sB[kk][tx * 4 + j];
            #pragma unroll
            for (int i = 0; i < 4; i++)
                #pragma unroll
                for (int j = 0; j < 4; j++)
                    acc[i][j] += a[i] * b[j];
        }
        __syncthreads();
    }
    #pragma unroll
    for (int i = 0; i < 4; i++) {
        int gm = m0 + ty * 4 + i;
        if (gm >= NN) break;
        #pragma unroll
        for (int j = 0; j < 4; j++) {
            int gn = n0 + tx * 4 + j;
            float v = acc[i][j];
            if (bias1) v += bias1[gn];
            if (bias2) v += bias2[gn];
            C[gm * 256 + gn] = v;
        }
    }
}

// ---------------- attention logit contributions (layer 1) ----------------
// warp per node: als[n,h] = sum_c h1[n,h,c]*asrc[h,c]; similarly ald
__global__ void compute_al(const float* __restrict__ asrc, const float* __restrict__ adst) {
    int warp = (blockIdx.x * blockDim.x + threadIdx.x) >> 5;
    int lane = threadIdx.x & 31;
    if (warp >= NN) return;
    const float4* hr = (const float4*)&d_h1[warp * 256];
    int head = lane >> 3;          // 8 lanes per head (64 channels)
    float s = 0.f, d = 0.f;
    #pragma unroll
    for (int q = 0; q < 2; q++) {
        float4 hv = hr[lane * 2 + q];
        int cbase = (lane * 8 + q * 4) & 63;
        const float* as = asrc + head * 64 + cbase;
        const float* ad = adst + head * 64 + cbase;
        s += hv.x * as[0] + hv.y * as[1] + hv.z * as[2] + hv.w * as[3];
        d += hv.x * ad[0] + hv.y * ad[1] + hv.z * ad[2] + hv.w * ad[3];
    }
    #pragma unroll
    for (int off = 4; off > 0; off >>= 1) {
        s += __shfl_down_sync(0xffffffff, s, off);
        d += __shfl_down_sync(0xffffffff, d, off);
    }
    if ((lane & 7) == 0) {
        ((float*)&d_als1[warp])[head] = s;
        ((float*)&d_ald1[warp])[head] = d;
    }
}

// ---------------- edge softmax numerator + denominator (layer 1) ----------------
// NOTE: segment_max is skipped — softmax is shift-invariant and logits here are
// bounded (|e| < ~6), so exp without max-subtraction is exact to fp32.
__global__ void edge_pass1_l1(const int* __restrict__ ei) {
    int e = blockIdx.x * blockDim.x + threadIdx.x;
    if (e >= EE) return;
    int s = ei[e], t = ei[EE + e];
    float4 a = d_als1[s], b = d_ald1[t];
    float4 ex;
    ex.x = __expf(lrelu(a.x + b.x));
    ex.y = __expf(lrelu(a.y + b.y));
    ex.z = __expf(lrelu(a.z + b.z));
    ex.w = __expf(lrelu(a.w + b.w));
    d_ex1[e] = ex;
    float* dn = (float*)&d_denom1[t];
    atomicAdd(dn + 0, ex.x);
    atomicAdd(dn + 1, ex.y);
    atomicAdd(dn + 2, ex.z);
    atomicAdd(dn + 3, ex.w);
}

// ---------------- message aggregation (layer 1): block per edge, 256 ch ----------------
__global__ void edge_msg_l1(const int* __restrict__ ei) {
    int e = blockIdx.x;
    int t = threadIdx.x;
    int s = ei[e], dnode = ei[EE + e];
    int h = t >> 6;
    float ex = ((const float*)&d_ex1[e])[h];
    float den = ((const float*)&d_denom1[dnode])[h];
    float alpha = ex / (den + 1e-16f);
    atomicAdd(&d_y1[dnode * 256 + t], alpha * d_h1[s * 256 + t]);
}

__global__ void relu_k(float* __restrict__ p, int n) {
    int i = blockIdx.x * blockDim.x + threadIdx.x;
    if (i < n) p[i] = fmaxf(p[i], 0.f);
}

// ---------------- layer 2 row kernel: warp per node ----------------
__global__ void layer2_row(const float* __restrict__ lin3W, const float* __restrict__ lin3b,
                           const float* __restrict__ con3W, const float* __restrict__ asrc,
                           const float* __restrict__ adst, const float* __restrict__ con3b,
                           float* __restrict__ out) {
    int warp = (blockIdx.x * blockDim.x + threadIdx.x) >> 5;
    int lane = threadIdx.x & 31;
    if (warp >= NN) return;
    const float* row = d_xn + warp * 256;
    float y0 = 0.f, y1v = 0.f, h0 = 0.f, h1v = 0.f;
    for (int c = lane; c < 256; c += 32) {
        float v = row[c];
        y0  += v * lin3W[c * 2];
        y1v += v * lin3W[c * 2 + 1];
        h0  += v * con3W[c * 2];
        h1v += v * con3W[c * 2 + 1];
    }
    #pragma unroll
    for (int off = 16; off > 0; off >>= 1) {
        y0  += __shfl_xor_sync(0xffffffff, y0,  off);
        y1v += __shfl_xor_sync(0xffffffff, y1v, off);
        h0  += __shfl_xor_sync(0xffffffff, h0,  off);
        h1v += __shfl_xor_sync(0xffffffff, h1v, off);
    }
    if (lane == 0) {
        out[warp * 2]     = y0  + lin3b[0] + con3b[0];
        out[warp * 2 + 1] = y1v + lin3b[1] + con3b[1];
        d_h3[warp] = make_float2(h0, h1v);
        d_als3[warp] = h0 * asrc[0] + h1v * asrc[1];
        d_ald3[warp] = h0 * adst[0] + h1v * adst[1];
    }
}

__global__ void edge_pass1_l2(const int* __restrict__ ei) {
    int e = blockIdx.x * blockDim.x + threadIdx.x;
    if (e >= EE) return;
    int s = ei[e], t = ei[EE + e];
    float ex = __expf(lrelu(d_als3[s] + d_ald3[t]));
    d_ex3[e] = ex;
    atomicAdd(&d_denom3[t], ex);
}

__global__ void edge_msg_l2(const int* __restrict__ ei, float* __restrict__ out) {
    int e = blockIdx.x * blockDim.x + threadIdx.x;
    if (e >= EE) return;
    int s = ei[e], t = ei[EE + e];
    float alpha = d_ex3[e] / (d_denom3[t] + 1e-16f);
    float2 h = d_h3[s];
    atomicAdd(&out[t * 2],     alpha * h.x);
    atomicAdd(&out[t * 2 + 1], alpha * h.y);
}

// ---------------- launch ----------------
extern "C" void kernel_launch(void* const* d_in, const int* in_sizes, int n_in,
                              void* d_out, int out_size) {
    const float* x         = (const float*)d_in[0];
    const int*   ei        = (const int*)d_in[1];
    const float* bn1_g     = (const float*)d_in[2];
    const float* bn1_b     = (const float*)d_in[3];
    const float* lin1_W    = (const float*)d_in[4];
    const float* lin1_b    = (const float*)d_in[5];
    const float* con1_W    = (const float*)d_in[6];
    const float* con1_asrc = (const float*)d_in[7];
    const float* con1_adst = (const float*)d_in[8];
    const float* con1_b    = (const float*)d_in[9];
    const float* bn3_g     = (const float*)d_in[10];
    const float* bn3_b     = (const float*)d_in[11];
    const float* lin3_W    = (const float*)d_in[12];
    const float* lin3_b    = (const float*)d_in[13];
    const float* con3_W    = (const float*)d_in[14];
    const float* con3_asrc = (const float*)d_in[15];
    const float* con3_adst = (const float*)d_in[16];
    const float* con3_b    = (const float*)d_in[17];
    float* out = (float*)d_out;

    // Get device pointers to __device__ globals for kernel args where needed
    float* p_xn; cudaGetSymbolAddress((void**)&p_xn, d_xn);
    float* p_y1; cudaGetSymbolAddress((void**)&p_y1, d_y1);
    float* p_h1; cudaGetSymbolAddress((void**)&p_h1, d_h1);

    const int elemgrid = (NN * FDIM + 255) / 256;

    // zero accumulators (both layers' denominators + BN sums)
    zero_denoms<<<(NN * 4 + 255) / 256, 256>>>();
    zero_bn<<<1, 256>>>();

    // BN1 -> xn
    bn_stats<<<512, 256>>>(x);
    bn_finalize<<<1, 256>>>(bn1_g, bn1_b);
    bn_apply<<<elemgrid, 256>>>(x, p_xn);

    // linear1 (+lin1_b +con1_b fused) and GAT1 feature transform
    gemm256<<<dim3((NN + 63) / 64, 4), 256>>>(p_xn, lin1_W, lin1_b, con1_b, p_y1);
    gemm256<<<dim3((NN + 63) / 64, 4), 256>>>(p_xn, con1_W, nullptr, nullptr, p_h1);

    // GAT1 attention
    compute_al<<<(NN + 7) / 8, 256>>>(con1_asrc, con1_adst);
    edge_pass1_l1<<<(EE + 255) / 256, 256>>>(ei);
    edge_msg_l1<<<EE, 256>>>(ei);

    // relu -> x1 (in d_y1)
    relu_k<<<elemgrid, 256>>>(p_y1, NN * FDIM);

    // BN3 -> xn2 (reuse d_xn)
    zero_bn<<<1, 256>>>();
    bn_stats<<<512, 256>>>(p_y1);
    bn_finalize<<<1, 256>>>(bn3_g, bn3_b);
    bn_apply<<<elemgrid, 256>>>(p_y1, p_xn);

    // layer 2: linear3 + GAT2 features/logits fused per-row
    layer2_row<<<(NN + 7) / 8, 256>>>(lin3_W, lin3_b, con3_W, con3_asrc, con3_adst, con3_b, out);
    edge_pass1_l2<<<(EE + 255) / 256, 256>>>(ei);
    edge_msg_l2<<<(EE + 255) / 256, 256>>>(ei, out);

    // final relu
    relu_k<<<(NN * 2 + 255) / 256, 256>>>(out, NN * 2);
}

// round 3
// speedup vs baseline: 1.0027x; 1.0027x over previous
#include <cuda_runtime.h>
#include <cuda_bf16.h>

#define NN 50000
#define EE 800000
#define FDIM 256     // IN == HID*HEADS == 256
#define HEADS 4
#define HID 64

// ---------------- scratch (static device globals; allocation-free) ----------------
__device__ float  d_xn[NN * FDIM];     // normalized features (reused for layer 2)
__device__ float  d_y1[NN * FDIM];     // linear output / accumulation target / x1
__device__ float  d_h1[NN * FDIM];     // GAT1 transformed features
__device__ float4 d_als1[NN];
__device__ float4 d_ald1[NN];
__device__ float4 d_denom1[NN];
__device__ float4 d_ex1[EE];
__device__ float2 d_h3[NN];
__device__ float  d_als3[NN];
__device__ float  d_ald3[NN];
__device__ float  d_denom3[NN];
__device__ float  d_ex3[EE];
__device__ float  d_bnsum[FDIM];
__device__ float  d_bnsumsq[FDIM];
__device__ float  d_scale[FDIM];
__device__ float  d_shift[FDIM];

__device__ __forceinline__ float lrelu(float x) { return x > 0.f ? x : 0.2f * x; }

// ---------------- zeroing ----------------
__global__ void zero_bn() {
    d_bnsum[threadIdx.x] = 0.f;
    d_bnsumsq[threadIdx.x] = 0.f;
}

__global__ void zero_denoms() {
    int i = blockIdx.x * blockDim.x + threadIdx.x;
    if (i < NN * 4) ((float*)d_denom1)[i] = 0.f;
    if (i < NN) d_denom3[i] = 0.f;
}

// ---------------- batchnorm ----------------
__global__ void bn_stats(const float* __restrict__ x) {
    int c = threadIdx.x;
    float s = 0.f, s2 = 0.f;
    for (int r = blockIdx.x; r < NN; r += gridDim.x) {
        float v = x[r * FDIM + c];
        s += v; s2 += v * v;
    }
    atomicAdd(&d_bnsum[c], s);
    atomicAdd(&d_bnsumsq[c], s2);
}

__global__ void bn_finalize(const float* __restrict__ g, const float* __restrict__ b) {
    int c = threadIdx.x;
    const float invn = 1.0f / (float)NN;
    float mu = d_bnsum[c] * invn;
    float var = d_bnsumsq[c] * invn - mu * mu;
    float rs = rsqrtf(var + 1e-5f);
    float sc = rs * g[c];
    d_scale[c] = sc;
    d_shift[c] = b[c] - mu * sc;
}

__global__ void bn_apply(const float* __restrict__ x, float* __restrict__ xo) {
    int i = blockIdx.x * blockDim.x + threadIdx.x;
    if (i < NN * FDIM) {
        int c = i & (FDIM - 1);
        xo[i] = x[i] * d_scale[c] + d_shift[c];
    }
}

// ---------------- GEMM: C[M,256] = A[M,256] @ B[256,256] (+ bias1 + bias2) ----------------
// 64x64 tile, TK=16, 256 threads, 4x4 micro-tile per thread
__global__ void gemm256(const float* __restrict__ A, const float* __restrict__ B,
                        const float* __restrict__ bias1, const float* __restrict__ bias2,
                        float* __restrict__ C) {
    __shared__ float sA[16][65];
    __shared__ float sB[16][64];
    int t = threadIdx.x;
    int tx = t & 15, ty = t >> 4;
    int m0 = blockIdx.x * 64, n0 = blockIdx.y * 64;
    float acc[4][4] = {};

    for (int k0 = 0; k0 < 256; k0 += 16) {
        // load A tile (coalesced along k within a row)
        #pragma unroll
        for (int j = 0; j < 4; j++) {
            int i = t + j * 256;
            int k = i & 15, m = i >> 4;
            int gm = m0 + m;
            sA[k][m] = (gm < NN) ? A[gm * 256 + k0 + k] : 0.f;
        }
        // load B tile (coalesced along n)
        #pragma unroll
        for (int j = 0; j < 4; j++) {
            int i = t + j * 256;
            int n = i & 63, k = i >> 6;
            sB[k][n] = B[(k0 + k) * 256 + n0 + n];
        }
        __syncthreads();
        #pragma unroll
        for (int kk = 0; kk < 16; kk++) {
            float a[4], b[4];
            #pragma unroll
            for (int i = 0; i < 4; i++) a[i] = sA[kk][ty * 4 + i];
            #pragma unroll
            for (int j = 0; j < 4; j++) b[j] = sB[kk][tx * 4 + j];
            #pragma unroll
            for (int i = 0; i < 4; i++)
                #pragma unroll
                for (int j = 0; j < 4; j++)
                    acc[i][j] += a[i] * b[j];
        }
        __syncthreads();
    }
    #pragma unroll
    for (int i = 0; i < 4; i++) {
        int gm = m0 + ty * 4 + i;
        if (gm >= NN) break;
        #pragma unroll
        for (int j = 0; j < 4; j++) {
            int gn = n0 + tx * 4 + j;
            float v = acc[i][j];
            if (bias1) v += bias1[gn];
            if (bias2) v += bias2[gn];
            C[gm * 256 + gn] = v;
        }
    }
}

// ---------------- attention logit contributions (layer 1) ----------------
// warp per node: als[n,h] = sum_c h1[n,h,c]*asrc[h,c]; similarly ald
__global__ void compute_al(const float* __restrict__ asrc, const float* __restrict__ adst) {
    int warp = (blockIdx.x * blockDim.x + threadIdx.x) >> 5;
    int lane = threadIdx.x & 31;
    if (warp >= NN) return;
    const float4* hr = (const float4*)&d_h1[warp * 256];
    int head = lane >> 3;          // 8 lanes per head (64 channels)
    float s = 0.f, d = 0.f;
    #pragma unroll
    for (int q = 0; q < 2; q++) {
        float4 hv = hr[lane * 2 + q];
        int cbase = (lane * 8 + q * 4) & 63;
        const float* as = asrc + head * 64 + cbase;
        const float* ad = adst + head * 64 + cbase;
        s += hv.x * as[0] + hv.y * as[1] + hv.z * as[2] + hv.w * as[3];
        d += hv.x * ad[0] + hv.y * ad[1] + hv.z * ad[2] + hv.w * ad[3];
    }
    #pragma unroll
    for (int off = 4; off > 0; off >>= 1) {
        s += __shfl_down_sync(0xffffffff, s, off);
        d += __shfl_down_sync(0xffffffff, d, off);
    }
    if ((lane & 7) == 0) {
        ((float*)&d_als1[warp])[head] = s;
        ((float*)&d_ald1[warp])[head] = d;
    }
}

// ---------------- edge softmax numerator + denominator (layer 1) ----------------
// NOTE: segment_max is skipped — softmax is shift-invariant and logits here are
// bounded (|e| < ~6), so exp without max-subtraction is exact to fp32.
__global__ void edge_pass1_l1(const int* __restrict__ ei) {
    int e = blockIdx.x * blockDim.x + threadIdx.x;
    if (e >= EE) return;
    int s = ei[e], t = ei[EE + e];
    float4 a = d_als1[s], b = d_ald1[t];
    float4 ex;
    ex.x = __expf(lrelu(a.x + b.x));
    ex.y = __expf(lrelu(a.y + b.y));
    ex.z = __expf(lrelu(a.z + b.z));
    ex.w = __expf(lrelu(a.w + b.w));
    d_ex1[e] = ex;
    float* dn = (float*)&d_denom1[t];
    atomicAdd(dn + 0, ex.x);
    atomicAdd(dn + 1, ex.y);
    atomicAdd(dn + 2, ex.z);
    atomicAdd(dn + 3, ex.w);
}

// ---------------- message aggregation (layer 1): block per edge, 256 ch ----------------
__global__ void edge_msg_l1(const int* __restrict__ ei) {
    int e = blockIdx.x;
    int t = threadIdx.x;
    int s = ei[e], dnode = ei[EE + e];
    int h = t >> 6;
    float ex = ((const float*)&d_ex1[e])[h];
    float den = ((const float*)&d_denom1[dnode])[h];
    float alpha = ex / (den + 1e-16f);
    atomicAdd(&d_y1[dnode * 256 + t], alpha * d_h1[s * 256 + t]);
}

__global__ void relu_k(float* __restrict__ p, int n) {
    int i = blockIdx.x * blockDim.x + threadIdx.x;
    if (i < n) p[i] = fmaxf(p[i], 0.f);
}

// ---------------- layer 2 row kernel: warp per node ----------------
__global__ void layer2_row(const float* __restrict__ lin3W, const float* __restrict__ lin3b,
                           const float* __restrict__ con3W, const float* __restrict__ asrc,
                           const float* __restrict__ adst, const float* __restrict__ con3b,
                           float* __restrict__ out) {
    int warp = (blockIdx.x * blockDim.x + threadIdx.x) >> 5;
    int lane = threadIdx.x & 31;
    if (warp >= NN) return;
    const float* row = d_xn + warp * 256;
    float y0 = 0.f, y1v = 0.f, h0 = 0.f, h1v = 0.f;
    for (int c = lane; c < 256; c += 32) {
        float v = row[c];
        y0  += v * lin3W[c * 2];
        y1v += v * lin3W[c * 2 + 1];
        h0  += v * con3W[c * 2];
        h1v += v * con3W[c * 2 + 1];
    }
    #pragma unroll
    for (int off = 16; off > 0; off >>= 1) {
        y0  += __shfl_xor_sync(0xffffffff, y0,  off);
        y1v += __shfl_xor_sync(0xffffffff, y1v, off);
        h0  += __shfl_xor_sync(0xffffffff, h0,  off);
        h1v += __shfl_xor_sync(0xffffffff, h1v, off);
    }
    if (lane == 0) {
        out[warp * 2]     = y0  + lin3b[0] + con3b[0];
        out[warp * 2 + 1] = y1v + lin3b[1] + con3b[1];
        d_h3[warp] = make_float2(h0, h1v);
        d_als3[warp] = h0 * asrc[0] + h1v * asrc[1];
        d_ald3[warp] = h0 * adst[0] + h1v * adst[1];
    }
}

__global__ void edge_pass1_l2(const int* __restrict__ ei) {
    int e = blockIdx.x * blockDim.x + threadIdx.x;
    if (e >= EE) return;
    int s = ei[e], t = ei[EE + e];
    float ex = __expf(lrelu(d_als3[s] + d_ald3[t]));
    d_ex3[e] = ex;
    atomicAdd(&d_denom3[t], ex);
}

__global__ void edge_msg_l2(const int* __restrict__ ei, float* __restrict__ out) {
    int e = blockIdx.x * blockDim.x + threadIdx.x;
    if (e >= EE) return;
    int s = ei[e], t = ei[EE + e];
    float alpha = d_ex3[e] / (d_denom3[t] + 1e-16f);
    float2 h = d_h3[s];
    atomicAdd(&out[t * 2],     alpha * h.x);
    atomicAdd(&out[t * 2 + 1], alpha * h.y);
}

// ---------------- launch ----------------
extern "C" void kernel_launch(void* const* d_in, const int* in_sizes, int n_in,
                              void* d_out, int out_size) {
    const float* x         = (const float*)d_in[0];
    const int*   ei        = (const int*)d_in[1];
    const float* bn1_g     = (const float*)d_in[2];
    const float* bn1_b     = (const float*)d_in[3];
    const float* lin1_W    = (const float*)d_in[4];
    const float* lin1_b    = (const float*)d_in[5];
    const float* con1_W    = (const float*)d_in[6];
    const float* con1_asrc = (const float*)d_in[7];
    const float* con1_adst = (const float*)d_in[8];
    const float* con1_b    = (const float*)d_in[9];
    const float* bn3_g     = (const float*)d_in[10];
    const float* bn3_b     = (const float*)d_in[11];
    const float* lin3_W    = (const float*)d_in[12];
    const float* lin3_b    = (const float*)d_in[13];
    const float* con3_W    = (const float*)d_in[14];
    const float* con3_asrc = (const float*)d_in[15];
    const float* con3_adst = (const float*)d_in[16];
    const float* con3_b    = (const float*)d_in[17];
    float* out = (float*)d_out;

    // Get device pointers to __device__ globals for kernel args where needed
    float* p_xn; cudaGetSymbolAddress((void**)&p_xn, d_xn);
    float* p_y1; cudaGetSymbolAddress((void**)&p_y1, d_y1);
    float* p_h1; cudaGetSymbolAddress((void**)&p_h1, d_h1);

    const int elemgrid = (NN * FDIM + 255) / 256;

    // zero accumulators (both layers' denominators + BN sums)
    zero_denoms<<<(NN * 4 + 255) / 256, 256>>>();
    zero_bn<<<1, 256>>>();

    // BN1 -> xn
    bn_stats<<<512, 256>>>(x);
    bn_finalize<<<1, 256>>>(bn1_g, bn1_b);
    bn_apply<<<elemgrid, 256>>>(x, p_xn);

    // linear1 (+lin1_b +con1_b fused) and GAT1 feature transform
    gemm256<<<dim3((NN + 63) / 64, 4), 256>>>(p_xn, lin1_W, lin1_b, con1_b, p_y1);
    gemm256<<<dim3((NN + 63) / 64, 4), 256>>>(p_xn, con1_W, nullptr, nullptr, p_h1);

    // GAT1 attention
    compute_al<<<(NN + 7) / 8, 256>>>(con1_asrc, con1_adst);
    edge_pass1_l1<<<(EE + 255) / 256, 256>>>(ei);
    edge_msg_l1<<<EE, 256>>>(ei);

    // relu -> x1 (in d_y1)
    relu_k<<<elemgrid, 256>>>(p_y1, NN * FDIM);

    // BN3 -> xn2 (reuse d_xn)
    zero_bn<<<1, 256>>>();
    bn_stats<<<512, 256>>>(p_y1);
    bn_finalize<<<1, 256>>>(bn3_g, bn3_b);
    bn_apply<<<elemgrid, 256>>>(p_y1, p_xn);

    // layer 2: linear3 + GAT2 features/logits fused per-row
    layer2_row<<<(NN + 7) / 8, 256>>>(lin3_W, lin3_b, con3_W, con3_asrc, con3_adst, con3_b, out);
    edge_pass1_l2<<<(EE + 255) / 256, 256>>>(ei);
    edge_msg_l2<<<(EE + 255) / 256, 256>>>(ei, out);

    // final relu
    relu_k<<<(NN * 2 + 255) / 256, 256>>>(out, NN * 2);
}

// round 4
// speedup vs baseline: 2.1742x; 2.1683x over previous
#include <cuda_runtime.h>
#include <cuda_bf16.h>

#define NN 50000
#define EE 800000
#define FDIM 256
#define HEADS 4
#define HID 64

// ---------------- scratch (static device globals; allocation-free) ----------------
__device__ float  d_y1[NN * FDIM];     // linear1 output + GAT1 aggregation -> x1
__device__ float  d_h1[NN * FDIM];     // GAT1 transformed features
__device__ float4 d_als1[NN];
__device__ float4 d_ald1[NN];
__device__ float4 d_rden1[NN];         // reciprocal denominators
__device__ float4 d_ex1[EE];           // softmax numerators, CSR edge order
__device__ float2 d_h3[NN];
__device__ float  d_als3[NN];
__device__ float  d_ald3[NN];
__device__ float  d_bnsum[FDIM];
__device__ float  d_bnsumsq[FDIM];
__device__ float  d_scale[FDIM];
__device__ float  d_shift[FDIM];
// CSR (dst-sorted)
__device__ int d_rowptr[NN + 1];
__device__ int d_cursor[NN];
__device__ int d_csr_src[EE];
__device__ int d_chunksum[64];

__device__ __forceinline__ float lrelu(float x) { return x > 0.f ? x : 0.2f * x; }

// ---------------- zeroing ----------------
__global__ void zero_all() {
    int i = blockIdx.x * blockDim.x + threadIdx.x;
    if (i < NN + 1) d_rowptr[i] = 0;
    if (i < FDIM) { d_bnsum[i] = 0.f; d_bnsumsq[i] = 0.f; }
}
__global__ void zero_bn() {
    d_bnsum[threadIdx.x] = 0.f;
    d_bnsumsq[threadIdx.x] = 0.f;
}

// ---------------- CSR build ----------------
__global__ void hist_k(const int* __restrict__ ei) {
    int e = blockIdx.x * blockDim.x + threadIdx.x;
    if (e < EE) atomicAdd(&d_rowptr[ei[EE + e] + 1], 1);
}
__global__ void scan1_k() {
    __shared__ int s[1024];
    int tid = threadIdx.x;
    int i = blockIdx.x * 1024 + tid;
    int v = (i <= NN) ? d_rowptr[i] : 0;
    s[tid] = v;
    __syncthreads();
    #pragma unroll
    for (int off = 1; off < 1024; off <<= 1) {
        int add = (tid >= off) ? s[tid - off] : 0;
        __syncthreads();
        s[tid] += add;
        __syncthreads();
    }
    if (i <= NN) d_rowptr[i] = s[tid];
    if (tid == 1023) d_chunksum[blockIdx.x] = s[1023];
}
__global__ void scan2_k(int nchunks) {
    __shared__ int s[64];
    int tid = threadIdx.x;
    int v = (tid < nchunks) ? d_chunksum[tid] : 0;
    s[tid] = v;
    __syncthreads();
    #pragma unroll
    for (int off = 1; off < 64; off <<= 1) {
        int add = (tid >= off) ? s[tid - off] : 0;
        __syncthreads();
        s[tid] += add;
        __syncthreads();
    }
    d_chunksum[tid] = s[tid];
}
__global__ void scan3_k() {
    int chunk = blockIdx.x + 1;
    int i = chunk * 1024 + threadIdx.x;
    if (i <= NN) d_rowptr[i] += d_chunksum[chunk - 1];
}
__global__ void cursor_k() {
    int i = blockIdx.x * blockDim.x + threadIdx.x;
    if (i < NN) d_cursor[i] = d_rowptr[i];
}
__global__ void scatter_k(const int* __restrict__ ei) {
    int e = blockIdx.x * blockDim.x + threadIdx.x;
    if (e >= EE) return;
    int s = ei[e], t = ei[EE + e];
    int pos = atomicAdd(&d_cursor[t], 1);
    d_csr_src[pos] = s;
}

// ---------------- batchnorm stats ----------------
__global__ void bn_stats(const float* __restrict__ x, int dorelu) {
    const float* src = x ? x : (const float*)d_y1;
    int c = threadIdx.x;
    float s = 0.f, s2 = 0.f;
    for (int r = blockIdx.x; r < NN; r += gridDim.x) {
        float v = src[r * FDIM + c];
        if (dorelu) v = fmaxf(v, 0.f);
        s += v; s2 += v * v;
    }
    atomicAdd(&d_bnsum[c], s);
    atomicAdd(&d_bnsumsq[c], s2);
}
__global__ void bn_finalize(const float* __restrict__ g, const float* __restrict__ b) {
    int c = threadIdx.x;
    const float invn = 1.0f / (float)NN;
    float mu = d_bnsum[c] * invn;
    float var = d_bnsumsq[c] * invn - mu * mu;
    float rs = rsqrtf(var + 1e-5f);
    float sc = rs * g[c];
    d_scale[c] = sc;
    d_shift[c] = b[c] - mu * sc;
}

// ---------------- dual GEMM with fused BN on A and fused biases ----------------
// C0[y1] = BN(X) @ W0 + b0a + b0b ; C1[h1] = BN(X) @ W1
// tile 128x64, 256 threads, 8x4 microtile, register double-buffered
__global__ void __launch_bounds__(256)
gemm_dual(const float* __restrict__ X,
          const float* __restrict__ W0, const float* __restrict__ b0a,
          const float* __restrict__ b0b, const float* __restrict__ W1) {
    __shared__ float sA[16][128];
    __shared__ float sB[16][64];
    int t = threadIdx.x;
    int tx = t & 15;         // n quad
    int ty = t >> 4;         // m oct
    int m0 = blockIdx.x * 128;
    int mat = blockIdx.y >> 2;
    int n0 = (blockIdx.y & 3) * 64;
    const float* B = mat ? W1 : W0;
    float* C = mat ? d_h1 : d_y1;

    int arow = t >> 1;              // 0..127
    int akb  = (t & 1) * 8;         // 0 or 8 (8 consecutive k per thread)
    int brow = t >> 4;              // 0..15 (k)
    int bcol = (t & 15) * 4;        // 0..60

    float acc[8][4] = {};
    float4 pa0, pa1, pb;
    bool arow_ok = (m0 + arow) < NN;

    // prefetch tile 0
    {
        const float* p = X + (size_t)(m0 + arow) * 256 + akb;
        if (arow_ok) { pa0 = *(const float4*)p; pa1 = *(const float4*)(p + 4); }
        else { pa0 = make_float4(0,0,0,0); pa1 = pa0; }
        float4 sc0 = *(const float4*)&d_scale[akb], sc1 = *(const float4*)&d_scale[akb + 4];
        float4 sh0 = *(const float4*)&d_shift[akb], sh1 = *(const float4*)&d_shift[akb + 4];
        if (arow_ok) {
            pa0.x = pa0.x*sc0.x+sh0.x; pa0.y = pa0.y*sc0.y+sh0.y;
            pa0.z = pa0.z*sc0.z+sh0.z; pa0.w = pa0.w*sc0.w+sh0.w;
            pa1.x = pa1.x*sc1.x+sh1.x; pa1.y = pa1.y*sc1.y+sh1.y;
            pa1.z = pa1.z*sc1.z+sh1.z; pa1.w = pa1.w*sc1.w+sh1.w;
        }
        pb = *(const float4*)&B[(size_t)brow * 256 + n0 + bcol];
    }
    // store tile 0
    sA[akb + 0][arow] = pa0.x; sA[akb + 1][arow] = pa0.y;
    sA[akb + 2][arow] = pa0.z; sA[akb + 3][arow] = pa0.w;
    sA[akb + 4][arow] = pa1.x; sA[akb + 5][arow] = pa1.y;
    sA[akb + 6][arow] = pa1.z; sA[akb + 7][arow] = pa1.w;
    *(float4*)&sB[brow][bcol] = pb;
    __syncthreads();

    for (int kt = 0; kt < 16; kt++) {
        int k0 = (kt + 1) * 16;
        if (kt < 15) {
            const float* p = X + (size_t)(m0 + arow) * 256 + k0 + akb;
            if (arow_ok) { pa0 = *(const float4*)p; pa1 = *(const float4*)(p + 4); }
            else { pa0 = make_float4(0,0,0,0); pa1 = pa0; }
            float4 sc0 = *(const float4*)&d_scale[k0 + akb], sc1 = *(const float4*)&d_scale[k0 + akb + 4];
            float4 sh0 = *(const float4*)&d_shift[k0 + akb], sh1 = *(const float4*)&d_shift[k0 + akb + 4];
            if (arow_ok) {
                pa0.x = pa0.x*sc0.x+sh0.x; pa0.y = pa0.y*sc0.y+sh0.y;
                pa0.z = pa0.z*sc0.z+sh0.z; pa0.w = pa0.w*sc0.w+sh0.w;
                pa1.x = pa1.x*sc1.x+sh1.x; pa1.y = pa1.y*sc1.y+sh1.y;
                pa1.z = pa1.z*sc1.z+sh1.z; pa1.w = pa1.w*sc1.w+sh1.w;
            }
            pb = *(const float4*)&B[(size_t)(k0 + brow) * 256 + n0 + bcol];
        }
        #pragma unroll
        for (int kk = 0; kk < 16; kk++) {
            float4 a0 = *(float4*)&sA[kk][ty * 8];
            float4 a1 = *(float4*)&sA[kk][ty * 8 + 4];
            float4 bq = *(float4*)&sB[kk][tx * 4];
            float a[8] = {a0.x,a0.y,a0.z,a0.w,a1.x,a1.y,a1.z,a1.w};
            float b[4] = {bq.x,bq.y,bq.z,bq.w};
            #pragma unroll
            for (int i = 0; i < 8; i++)
                #pragma unroll
                for (int j = 0; j < 4; j++)
                    acc[i][j] += a[i] * b[j];
        }
        __syncthreads();
        if (kt < 15) {
            sA[akb + 0][arow] = pa0.x; sA[akb + 1][arow] = pa0.y;
            sA[akb + 2][arow] = pa0.z; sA[akb + 3][arow] = pa0.w;
            sA[akb + 4][arow] = pa1.x; sA[akb + 5][arow] = pa1.y;
            sA[akb + 6][arow] = pa1.z; sA[akb + 7][arow] = pa1.w;
            *(float4*)&sB[brow][bcol] = pb;
            __syncthreads();
        }
    }

    float4 bias = make_float4(0,0,0,0);
    if (!mat) {
        int gn = n0 + tx * 4;
        float4 v1 = *(const float4*)&b0a[gn];
        float4 v2 = *(const float4*)&b0b[gn];
        bias = make_float4(v1.x+v2.x, v1.y+v2.y, v1.z+v2.z, v1.w+v2.w);
    }
    #pragma unroll
    for (int i = 0; i < 8; i++) {
        int gm = m0 + ty * 8 + i;
        if (gm < NN) {
            float4 v = make_float4(acc[i][0]+bias.x, acc[i][1]+bias.y,
                                   acc[i][2]+bias.z, acc[i][3]+bias.w);
            *(float4*)&C[(size_t)gm * 256 + n0 + tx * 4] = v;
        }
    }
}

// ---------------- attention logit contributions (layer 1) ----------------
__global__ void compute_al(const float* __restrict__ asrc, const float* __restrict__ adst) {
    int warp = (blockIdx.x * blockDim.x + threadIdx.x) >> 5;
    int lane = threadIdx.x & 31;
    if (warp >= NN) return;
    const float4* hr = (const float4*)&d_h1[(size_t)warp * 256];
    int head = lane >> 3;
    float s = 0.f, d = 0.f;
    #pragma unroll
    for (int q = 0; q < 2; q++) {
        float4 hv = hr[lane * 2 + q];
        int cbase = (lane * 8 + q * 4) & 63;
        const float* as = asrc + head * 64 + cbase;
        const float* ad = adst + head * 64 + cbase;
        s += hv.x * as[0] + hv.y * as[1] + hv.z * as[2] + hv.w * as[3];
        d += hv.x * ad[0] + hv.y * ad[1] + hv.z * ad[2] + hv.w * ad[3];
    }
    #pragma unroll
    for (int off = 4; off > 0; off >>= 1) {
        s += __shfl_down_sync(0xffffffff, s, off);
        d += __shfl_down_sync(0xffffffff, d, off);
    }
    if ((lane & 7) == 0) {
        ((float*)&d_als1[warp])[head] = s;
        ((float*)&d_ald1[warp])[head] = d;
    }
}

// ---------------- layer-1 edge softmax per dst (warp/dst, no atomics) ----------------
__global__ void attn_l1() {
    int d = (blockIdx.x * blockDim.x + threadIdx.x) >> 5;
    int lane = threadIdx.x & 31;
    if (d >= NN) return;
    int b = d_rowptr[d], e = d_rowptr[d + 1];
    float4 ald = d_ald1[d];
    float sx = 0.f, sy = 0.f, sz = 0.f, sw = 0.f;
    for (int j = b + lane; j < e; j += 32) {
        int src = d_csr_src[j];
        float4 a = d_als1[src];
        float4 ex;
        ex.x = __expf(lrelu(a.x + ald.x));
        ex.y = __expf(lrelu(a.y + ald.y));
        ex.z = __expf(lrelu(a.z + ald.z));
        ex.w = __expf(lrelu(a.w + ald.w));
        d_ex1[j] = ex;
        sx += ex.x; sy += ex.y; sz += ex.z; sw += ex.w;
    }
    #pragma unroll
    for (int off = 16; off > 0; off >>= 1) {
        sx += __shfl_xor_sync(0xffffffff, sx, off);
        sy += __shfl_xor_sync(0xffffffff, sy, off);
        sz += __shfl_xor_sync(0xffffffff, sz, off);
        sw += __shfl_xor_sync(0xffffffff, sw, off);
    }
    if (lane == 0)
        d_rden1[d] = make_float4(1.f/(sx+1e-16f), 1.f/(sy+1e-16f),
                                 1.f/(sz+1e-16f), 1.f/(sw+1e-16f));
}

// ---------------- layer-1 message aggregation (block/dst, no atomics) ----------------
__global__ void msg_l1() {
    int d = blockIdx.x;
    int t = threadIdx.x;
    int h = t >> 6;
    int b = d_rowptr[d], e = d_rowptr[d + 1];
    if (b == e) return;
    float rd = ((const float*)&d_rden1[d])[h];
    __shared__ int   s_src[64];
    __shared__ float s_exf[256];
    const float* __restrict__ hp = (const float*)d_h1;
    float acc = 0.f;
    for (int c0 = b; c0 < e; c0 += 64) {
        int cnt = min(64, e - c0);
        if (t < cnt) s_src[t] = d_csr_src[c0 + t];
        if (t < cnt * 4) s_exf[t] = ((const float*)d_ex1)[c0 * 4 + t];
        __syncthreads();
        #pragma unroll 4
        for (int j = 0; j < cnt; j++) {
            float w = s_exf[j * 4 + h] * rd;
            acc += w * hp[(size_t)s_src[j] * 256 + t];
        }
        __syncthreads();
    }
    d_y1[(size_t)d * 256 + t] += acc;
}

// ---------------- layer 2: fused relu+BN + linear3 + GAT2 features/logits ----------------
__global__ void layer2_row(const float* __restrict__ lin3W, const float* __restrict__ lin3b,
                           const float* __restrict__ con3W, const float* __restrict__ asrc,
                           const float* __restrict__ adst, const float* __restrict__ con3b,
                           float* __restrict__ out) {
    int warp = (blockIdx.x * blockDim.x + threadIdx.x) >> 5;
    int lane = threadIdx.x & 31;
    if (warp >= NN) return;
    const float* row = (const float*)d_y1 + (size_t)warp * 256;
    float y0 = 0.f, y1v = 0.f, h0 = 0.f, h1v = 0.f;
    #pragma unroll
    for (int q = 0; q < 8; q++) {
        int c = lane + q * 32;
        float v = fmaxf(row[c], 0.f) * d_scale[c] + d_shift[c];
        y0  += v * lin3W[c * 2];
        y1v += v * lin3W[c * 2 + 1];
        h0  += v * con3W[c * 2];
        h1v += v * con3W[c * 2 + 1];
    }
    #pragma unroll
    for (int off = 16; off > 0; off >>= 1) {
        y0  += __shfl_xor_sync(0xffffffff, y0,  off);
        y1v += __shfl_xor_sync(0xffffffff, y1v, off);
        h0  += __shfl_xor_sync(0xffffffff, h0,  off);
        h1v += __shfl_xor_sync(0xffffffff, h1v, off);
    }
    if (lane == 0) {
        out[warp * 2]     = y0  + lin3b[0] + con3b[0];
        out[warp * 2 + 1] = y1v + lin3b[1] + con3b[1];
        d_h3[warp] = make_float2(h0, h1v);
        d_als3[warp] = h0 * asrc[0] + h1v * asrc[1];
        d_ald3[warp] = h0 * adst[0] + h1v * adst[1];
    }
}

// ---------------- layer-2 GAT: fully fused per dst (warp/dst, no atomics) ----------------
__global__ void gat_l2(float* __restrict__ out) {
    int d = (blockIdx.x * blockDim.x + threadIdx.x) >> 5;
    int lane = threadIdx.x & 31;
    if (d >= NN) return;
    int b = d_rowptr[d], e = d_rowptr[d + 1];
    float ald = d_ald3[d];
    float den = 0.f, m0 = 0.f, m1 = 0.f;
    for (int j = b + lane; j < e; j += 32) {
        int src = d_csr_src[j];
        float ex = __expf(lrelu(d_als3[src] + ald));
        float2 h = d_h3[src];
        den += ex; m0 += ex * h.x; m1 += ex * h.y;
    }
    #pragma unroll
    for (int off = 16; off > 0; off >>= 1) {
        den += __shfl_xor_sync(0xffffffff, den, off);
        m0  += __shfl_xor_sync(0xffffffff, m0,  off);
        m1  += __shfl_xor_sync(0xffffffff, m1,  off);
    }
    if (lane == 0) {
        float r = 1.f / (den + 1e-16f);
        out[d * 2]     += m0 * r;
        out[d * 2 + 1] += m1 * r;
    }
}

__global__ void relu_k(float* __restrict__ p, int n) {
    int i = blockIdx.x * blockDim.x + threadIdx.x;
    if (i < n) p[i] = fmaxf(p[i], 0.f);
}

// ---------------- launch ----------------
extern "C" void kernel_launch(void* const* d_in, const int* in_sizes, int n_in,
                              void* d_out, int out_size) {
    const float* x         = (const float*)d_in[0];
    const int*   ei        = (const int*)d_in[1];
    const float* bn1_g     = (const float*)d_in[2];
    const float* bn1_b     = (const float*)d_in[3];
    const float* lin1_W    = (const float*)d_in[4];
    const float* lin1_b    = (const float*)d_in[5];
    const float* con1_W    = (const float*)d_in[6];
    const float* con1_asrc = (const float*)d_in[7];
    const float* con1_adst = (const float*)d_in[8];
    const float* con1_b    = (const float*)d_in[9];
    const float* bn3_g     = (const float*)d_in[10];
    const float* bn3_b     = (const float*)d_in[11];
    const float* lin3_W    = (const float*)d_in[12];
    const float* lin3_b    = (const float*)d_in[13];
    const float* con3_W    = (const float*)d_in[14];
    const float* con3_asrc = (const float*)d_in[15];
    const float* con3_adst = (const float*)d_in[16];
    const float* con3_b    = (const float*)d_in[17];
    float* out = (float*)d_out;

    const int NCHUNK = (NN + 1 + 1023) / 1024;   // 49

    // zero counters + BN sums
    zero_all<<<(NN + 1 + 255) / 256, 256>>>();

    // CSR build
    hist_k<<<(EE + 255) / 256, 256>>>(ei);
    scan1_k<<<NCHUNK, 1024>>>();
    scan2_k<<<1, 64>>>(NCHUNK);
    scan3_k<<<NCHUNK - 1, 1024>>>();
    cursor_k<<<(NN + 255) / 256, 256>>>();
    scatter_k<<<(EE + 255) / 256, 256>>>(ei);

    // BN1 stats (applied inside GEMM)
    bn_stats<<<512, 256>>>(x, 0);
    bn_finalize<<<1, 256>>>(bn1_g, bn1_b);

    // fused dual GEMM: y1 = BN(x)@lin1_W + lin1_b + con1_b ; h1 = BN(x)@con1_W
    gemm_dual<<<dim3((NN + 127) / 128, 8), 256>>>(x, lin1_W, lin1_b, con1_b, con1_W);

    // GAT1 (atomic-free via CSR)
    compute_al<<<(NN + 7) / 8, 256>>>(con1_asrc, con1_adst);
    attn_l1<<<(NN + 7) / 8, 256>>>();
    msg_l1<<<NN, 256>>>();

    // BN3 stats (relu fused into read); relu+BN applied inside layer2_row
    zero_bn<<<1, 256>>>();
    bn_stats<<<512, 256>>>(nullptr, 1);
    bn_finalize<<<1, 256>>>(bn3_g, bn3_b);

    // layer 2
    layer2_row<<<(NN + 7) / 8, 256>>>(lin3_W, lin3_b, con3_W, con3_asrc, con3_adst, con3_b, out);
    gat_l2<<<(NN + 7) / 8, 256>>>(out);
    relu_k<<<(NN * 2 + 255) / 256, 256>>>(out, NN * 2);
}

// round 5
// speedup vs baseline: 2.8919x; 1.3301x over previous
#include <cuda_runtime.h>
#include <cuda_bf16.h>
#include <cstdint>

#define NN 50000
#define EE 800000
#define FDIM 256
#define HEADS 4
#define HID 64

// ---------------- scratch (static device globals; allocation-free) ----------------
__device__ float  d_y1[NN * FDIM];     // linear1 output + GAT1 aggregation -> x1
__device__ float  d_h1[NN * FDIM];     // GAT1 transformed features
__device__ __nv_bfloat16 d_a_hi[NN * FDIM];   // BN(x) in bf16 hi
__device__ __nv_bfloat16 d_a_lo[NN * FDIM];   // residual lo
__device__ __nv_bfloat16 d_w_hi[2 * FDIM * FDIM];  // [mat][n][k] transposed weights
__device__ __nv_bfloat16 d_w_lo[2 * FDIM * FDIM];
__device__ float4 d_als1[NN];
__device__ float4 d_ald1[NN];
__device__ float4 d_rden1[NN];
__device__ float4 d_ex1[EE];
__device__ float2 d_h3[NN];
__device__ float  d_als3[NN];
__device__ float  d_ald3[NN];
__device__ float  d_bnsum[FDIM];
__device__ float  d_bnsumsq[FDIM];
__device__ float  d_scale[FDIM];
__device__ float  d_shift[FDIM];
__device__ int d_rowptr[NN + 1];
__device__ int d_cursor[NN];
__device__ int d_csr_src[EE];
__device__ int d_chunksum[64];

__device__ __forceinline__ float lrelu(float x) { return x > 0.f ? x : 0.2f * x; }

// ---------------- zeroing ----------------
__global__ void zero_all() {
    int i = blockIdx.x * blockDim.x + threadIdx.x;
    if (i < NN + 1) d_rowptr[i] = 0;
    if (i < FDIM) { d_bnsum[i] = 0.f; d_bnsumsq[i] = 0.f; }
}
__global__ void zero_bn() {
    d_bnsum[threadIdx.x] = 0.f;
    d_bnsumsq[threadIdx.x] = 0.f;
}

// ---------------- CSR build ----------------
__global__ void hist_k(const int* __restrict__ ei) {
    int e = blockIdx.x * blockDim.x + threadIdx.x;
    if (e < EE) atomicAdd(&d_rowptr[ei[EE + e] + 1], 1);
}
__global__ void scan1_k() {
    __shared__ int s[1024];
    int tid = threadIdx.x;
    int i = blockIdx.x * 1024 + tid;
    int v = (i <= NN) ? d_rowptr[i] : 0;
    s[tid] = v;
    __syncthreads();
    #pragma unroll
    for (int off = 1; off < 1024; off <<= 1) {
        int add = (tid >= off) ? s[tid - off] : 0;
        __syncthreads();
        s[tid] += add;
        __syncthreads();
    }
    if (i <= NN) d_rowptr[i] = s[tid];
    if (tid == 1023) d_chunksum[blockIdx.x] = s[1023];
}
__global__ void scan2_k(int nchunks) {
    __shared__ int s[64];
    int tid = threadIdx.x;
    int v = (tid < nchunks) ? d_chunksum[tid] : 0;
    s[tid] = v;
    __syncthreads();
    #pragma unroll
    for (int off = 1; off < 64; off <<= 1) {
        int add = (tid >= off) ? s[tid - off] : 0;
        __syncthreads();
        s[tid] += add;
        __syncthreads();
    }
    d_chunksum[tid] = s[tid];
}
__global__ void scan3_k() {
    int chunk = blockIdx.x + 1;
    int i = chunk * 1024 + threadIdx.x;
    if (i <= NN) d_rowptr[i] += d_chunksum[chunk - 1];
}
__global__ void cursor_k() {
    int i = blockIdx.x * blockDim.x + threadIdx.x;
    if (i < NN) d_cursor[i] = d_rowptr[i];
}
__global__ void scatter_k(const int* __restrict__ ei) {
    int e = blockIdx.x * blockDim.x + threadIdx.x;
    if (e >= EE) return;
    int s = ei[e], t = ei[EE + e];
    int pos = atomicAdd(&d_cursor[t], 1);
    d_csr_src[pos] = s;
}

// ---------------- batchnorm stats ----------------
__global__ void bn_stats(const float* __restrict__ x, int dorelu) {
    const float* src = x ? x : (const float*)d_y1;
    int c = threadIdx.x;
    float s = 0.f, s2 = 0.f;
    for (int r = blockIdx.x; r < NN; r += gridDim.x) {
        float v = src[r * FDIM + c];
        if (dorelu) v = fmaxf(v, 0.f);
        s += v; s2 += v * v;
    }
    atomicAdd(&d_bnsum[c], s);
    atomicAdd(&d_bnsumsq[c], s2);
}
__global__ void bn_finalize(const float* __restrict__ g, const float* __restrict__ b) {
    int c = threadIdx.x;
    const float invn = 1.0f / (float)NN;
    float mu = d_bnsum[c] * invn;
    float var = d_bnsumsq[c] * invn - mu * mu;
    float rs = rsqrtf(var + 1e-5f);
    float sc = rs * g[c];
    d_scale[c] = sc;
    d_shift[c] = b[c] - mu * sc;
}

// ---------------- BN + bf16 hi/lo conversion of A ----------------
__global__ void bnconv(const float* __restrict__ x) {
    int i = blockIdx.x * blockDim.x + threadIdx.x;
    if (i >= NN * 64) return;
    int c = (i & 63) << 2;
    float4 v = ((const float4*)x)[i];
    float4 sc = *(const float4*)&d_scale[c];
    float4 sh = *(const float4*)&d_shift[c];
    float a0 = v.x * sc.x + sh.x, a1 = v.y * sc.y + sh.y;
    float a2 = v.z * sc.z + sh.z, a3 = v.w * sc.w + sh.w;
    __nv_bfloat16 h0 = __float2bfloat16_rn(a0), h1 = __float2bfloat16_rn(a1);
    __nv_bfloat16 h2 = __float2bfloat16_rn(a2), h3 = __float2bfloat16_rn(a3);
    __nv_bfloat162* ph = (__nv_bfloat162*)d_a_hi;
    ph[i * 2]     = __nv_bfloat162(h0, h1);
    ph[i * 2 + 1] = __nv_bfloat162(h2, h3);
    __nv_bfloat162* pl = (__nv_bfloat162*)d_a_lo;
    pl[i * 2]     = __nv_bfloat162(__float2bfloat16_rn(a0 - __bfloat162float(h0)),
                                   __float2bfloat16_rn(a1 - __bfloat162float(h1)));
    pl[i * 2 + 1] = __nv_bfloat162(__float2bfloat16_rn(a2 - __bfloat162float(h2)),
                                   __float2bfloat16_rn(a3 - __bfloat162float(h3)));
}

// ---------------- weight transpose + hi/lo conversion: W[k][n] -> Wt[n][k] ----------------
__global__ void wtconv(const float* __restrict__ W0, const float* __restrict__ W1) {
    int i = blockIdx.x * blockDim.x + threadIdx.x;
    if (i >= 2 * 65536) return;
    int mat = i >> 16, r = i & 65535;
    int n = r >> 8, k = r & 255;
    const float* W = mat ? W1 : W0;
    float v = W[k * 256 + n];
    __nv_bfloat16 h = __float2bfloat16_rn(v);
    d_w_hi[i] = h;
    d_w_lo[i] = __float2bfloat16_rn(v - __bfloat162float(h));
}

// ---------------- bf16 split tensor-core GEMM ----------------
#define SLDA 40

__device__ __forceinline__ void mma16816(float* d, const uint32_t* a, uint32_t b0, uint32_t b1) {
    asm volatile("mma.sync.aligned.m16n8k16.row.col.f32.bf16.bf16.f32 "
                 "{%0,%1,%2,%3}, {%4,%5,%6,%7}, {%8,%9}, {%0,%1,%2,%3};"
                 : "+f"(d[0]), "+f"(d[1]), "+f"(d[2]), "+f"(d[3])
                 : "r"(a[0]), "r"(a[1]), "r"(a[2]), "r"(a[3]), "r"(b0), "r"(b1));
}
__device__ __forceinline__ void ldsm4(uint32_t* r, uint32_t addr) {
    asm volatile("ldmatrix.sync.aligned.m8n8.x4.shared.b16 {%0,%1,%2,%3}, [%4];"
                 : "=r"(r[0]), "=r"(r[1]), "=r"(r[2]), "=r"(r[3]) : "r"(addr));
}

__global__ void __launch_bounds__(256, 1)
gemm_bf16(const float* __restrict__ b0a, const float* __restrict__ b0b) {
    __shared__ __nv_bfloat16 sA[2 * 128 * SLDA];
    __shared__ __nv_bfloat16 sB[2 * 128 * SLDA];
    int t = threadIdx.x;
    int m0 = blockIdx.x * 128;
    int mat = blockIdx.y >> 1;
    int n0 = (blockIdx.y & 1) * 128;
    const __nv_bfloat16* Bh = d_w_hi + mat * 65536;
    const __nv_bfloat16* Bl = d_w_lo + mat * 65536;
    float* C = mat ? d_h1 : d_y1;

    int lrow = t >> 1, seg = t & 1;
    int gm = m0 + lrow;
    bool aok = gm < NN;
    int gmc = aok ? gm : 0;
    const uint4* gAh = (const uint4*)(d_a_hi + (size_t)gmc * 256 + seg * 16);
    const uint4* gAl = (const uint4*)(d_a_lo + (size_t)gmc * 256 + seg * 16);
    const uint4* gBh = (const uint4*)(Bh + (size_t)(n0 + lrow) * 256 + seg * 16);
    const uint4* gBl = (const uint4*)(Bl + (size_t)(n0 + lrow) * 256 + seg * 16);

    uint4 ra0, ra1, ra2, ra3, rb0, rb1, rb2, rb3;
    const uint4 z4 = make_uint4(0, 0, 0, 0);

    ra0 = aok ? gAh[0] : z4; ra1 = aok ? gAh[1] : z4;
    ra2 = aok ? gAl[0] : z4; ra3 = aok ? gAl[1] : z4;
    rb0 = gBh[0]; rb1 = gBh[1]; rb2 = gBl[0]; rb3 = gBl[1];

    {
        uint4* pAh = (uint4*)(sA + lrow * SLDA + seg * 16);
        pAh[0] = ra0; pAh[1] = ra1;
        uint4* pAl = (uint4*)(sA + 128 * SLDA + lrow * SLDA + seg * 16);
        pAl[0] = ra2; pAl[1] = ra3;
        uint4* pBh = (uint4*)(sB + lrow * SLDA + seg * 16);
        pBh[0] = rb0; pBh[1] = rb1;
        uint4* pBl = (uint4*)(sB + 128 * SLDA + lrow * SLDA + seg * 16);
        pBl[0] = rb2; pBl[1] = rb3;
    }
    __syncthreads();

    int wid = t >> 5, lane = t & 31;
    int wm0 = (wid & 1) * 64, wn0 = (wid >> 1) * 32;
    float acc[4][4][4] = {};

    uint32_t sAu = (uint32_t)__cvta_generic_to_shared(sA);
    uint32_t sBu = (uint32_t)__cvta_generic_to_shared(sB);
    const uint32_t LOOFF = 128 * SLDA * 2;

    int a_r = (lane & 15);
    int a_c = (lane >> 4) << 3;
    int b_r = (lane & 7) + ((lane & 16) ? 8 : 0);
    int b_c = (lane & 8) ? 8 : 0;

    for (int s = 0; s < 8; s++) {
        if (s < 7) {
            int o = (s + 1) * 4;
            ra0 = aok ? gAh[o] : z4; ra1 = aok ? gAh[o + 1] : z4;
            ra2 = aok ? gAl[o] : z4; ra3 = aok ? gAl[o + 1] : z4;
            rb0 = gBh[o]; rb1 = gBh[o + 1]; rb2 = gBl[o]; rb3 = gBl[o + 1];
        }
        #pragma unroll
        for (int kk = 0; kk < 32; kk += 16) {
            uint32_t ah[4][4], al[4][4], bh[2][4], bl[2][4];
            #pragma unroll
            for (int i = 0; i < 4; i++) {
                uint32_t addr = sAu + (uint32_t)(((wm0 + i * 16 + a_r) * SLDA + kk + a_c) * 2);
                ldsm4(ah[i], addr);
                ldsm4(al[i], addr + LOOFF);
            }
            #pragma unroll
            for (int jp = 0; jp < 2; jp++) {
                uint32_t addr = sBu + (uint32_t)(((wn0 + jp * 16 + b_r) * SLDA + kk + b_c) * 2);
                ldsm4(bh[jp], addr);
                ldsm4(bl[jp], addr + LOOFF);
            }
            #pragma unroll
            for (int i = 0; i < 4; i++)
                #pragma unroll
                for (int j = 0; j < 4; j++) {
                    int jp = j >> 1, o = (j & 1) * 2;
                    mma16816(acc[i][j], ah[i], bh[jp][o], bh[jp][o + 1]);
                    mma16816(acc[i][j], ah[i], bl[jp][o], bl[jp][o + 1]);
                    mma16816(acc[i][j], al[i], bh[jp][o], bh[jp][o + 1]);
                }
        }
        if (s < 7) {
            __syncthreads();
            uint4* pAh = (uint4*)(sA + lrow * SLDA + seg * 16);
            pAh[0] = ra0; pAh[1] = ra1;
            uint4* pAl = (uint4*)(sA + 128 * SLDA + lrow * SLDA + seg * 16);
            pAl[0] = ra2; pAl[1] = ra3;
            uint4* pBh = (uint4*)(sB + lrow * SLDA + seg * 16);
            pBh[0] = rb0; pBh[1] = rb1;
            uint4* pBl = (uint4*)(sB + 128 * SLDA + lrow * SLDA + seg * 16);
            pBl[0] = rb2; pBl[1] = rb3;
            __syncthreads();
        }
    }

    int g = lane >> 2, tq = lane & 3;
    #pragma unroll
    for (int j = 0; j < 4; j++) {
        int gcol = n0 + wn0 + j * 8 + tq * 2;
        float bx = 0.f, by = 0.f;
        if (!mat) {
            bx = b0a[gcol] + b0b[gcol];
            by = b0a[gcol + 1] + b0b[gcol + 1];
        }
        #pragma unroll
        for (int i = 0; i < 4; i++) {
            int r0 = m0 + wm0 + i * 16 + g;
            if (r0 < NN)
                *(float2*)&C[(size_t)r0 * 256 + gcol] =
                    make_float2(acc[i][j][0] + bx, acc[i][j][1] + by);
            int r1 = r0 + 8;
            if (r1 < NN)
                *(float2*)&C[(size_t)r1 * 256 + gcol] =
                    make_float2(acc[i][j][2] + bx, acc[i][j][3] + by);
        }
    }
}

// ---------------- attention logit contributions (layer 1) ----------------
__global__ void compute_al(const float* __restrict__ asrc, const float* __restrict__ adst) {
    int warp = (blockIdx.x * blockDim.x + threadIdx.x) >> 5;
    int lane = threadIdx.x & 31;
    if (warp >= NN) return;
    const float4* hr = (const float4*)&d_h1[(size_t)warp * 256];
    int head = lane >> 3;
    float s = 0.f, d = 0.f;
    #pragma unroll
    for (int q = 0; q < 2; q++) {
        float4 hv = hr[lane * 2 + q];
        int cbase = (lane * 8 + q * 4) & 63;
        const float* as = asrc + head * 64 + cbase;
        const float* ad = adst + head * 64 + cbase;
        s += hv.x * as[0] + hv.y * as[1] + hv.z * as[2] + hv.w * as[3];
        d += hv.x * ad[0] + hv.y * ad[1] + hv.z * ad[2] + hv.w * ad[3];
    }
    #pragma unroll
    for (int off = 4; off > 0; off >>= 1) {
        s += __shfl_down_sync(0xffffffff, s, off);
        d += __shfl_down_sync(0xffffffff, d, off);
    }
    if ((lane & 7) == 0) {
        ((float*)&d_als1[warp])[head] = s;
        ((float*)&d_ald1[warp])[head] = d;
    }
}

// ---------------- layer-1 edge softmax per dst (warp/dst, no atomics) ----------------
__global__ void attn_l1() {
    int d = (blockIdx.x * blockDim.x + threadIdx.x) >> 5;
    int lane = threadIdx.x & 31;
    if (d >= NN) return;
    int b = d_rowptr[d], e = d_rowptr[d + 1];
    float4 ald = d_ald1[d];
    float sx = 0.f, sy = 0.f, sz = 0.f, sw = 0.f;
    for (int j = b + lane; j < e; j += 32) {
        int src = d_csr_src[j];
        float4 a = d_als1[src];
        float4 ex;
        ex.x = __expf(lrelu(a.x + ald.x));
        ex.y = __expf(lrelu(a.y + ald.y));
        ex.z = __expf(lrelu(a.z + ald.z));
        ex.w = __expf(lrelu(a.w + ald.w));
        d_ex1[j] = ex;
        sx += ex.x; sy += ex.y; sz += ex.z; sw += ex.w;
    }
    #pragma unroll
    for (int off = 16; off > 0; off >>= 1) {
        sx += __shfl_xor_sync(0xffffffff, sx, off);
        sy += __shfl_xor_sync(0xffffffff, sy, off);
        sz += __shfl_xor_sync(0xffffffff, sz, off);
        sw += __shfl_xor_sync(0xffffffff, sw, off);
    }
    if (lane == 0)
        d_rden1[d] = make_float4(1.f/(sx+1e-16f), 1.f/(sy+1e-16f),
                                 1.f/(sz+1e-16f), 1.f/(sw+1e-16f));
}

// ---------------- layer-1 message aggregation (block/dst, no atomics) ----------------
__global__ void msg_l1() {
    int d = blockIdx.x;
    int t = threadIdx.x;
    int h = t >> 6;
    int b = d_rowptr[d], e = d_rowptr[d + 1];
    if (b == e) return;
    float rd = ((const float*)&d_rden1[d])[h];
    __shared__ int   s_src[64];
    __shared__ float s_exf[256];
    const float* __restrict__ hp = (const float*)d_h1;
    float acc = 0.f;
    for (int c0 = b; c0 < e; c0 += 64) {
        int cnt = min(64, e - c0);
        if (t < cnt) s_src[t] = d_csr_src[c0 + t];
        if (t < cnt * 4) s_exf[t] = ((const float*)d_ex1)[c0 * 4 + t];
        __syncthreads();
        #pragma unroll 4
        for (int j = 0; j < cnt; j++) {
            float w = s_exf[j * 4 + h] * rd;
            acc += w * hp[(size_t)s_src[j] * 256 + t];
        }
        __syncthreads();
    }
    d_y1[(size_t)d * 256 + t] += acc;
}

// ---------------- layer 2: fused relu+BN + linear3 + GAT2 features/logits ----------------
__global__ void layer2_row(const float* __restrict__ lin3W, const float* __restrict__ lin3b,
                           const float* __restrict__ con3W, const float* __restrict__ asrc,
                           const float* __restrict__ adst, const float* __restrict__ con3b,
                           float* __restrict__ out) {
    int warp = (blockIdx.x * blockDim.x + threadIdx.x) >> 5;
    int lane = threadIdx.x & 31;
    if (warp >= NN) return;
    const float* row = (const float*)d_y1 + (size_t)warp * 256;
    float y0 = 0.f, y1v = 0.f, h0 = 0.f, h1v = 0.f;
    #pragma unroll
    for (int q = 0; q < 8; q++) {
        int c = lane + q * 32;
        float v = fmaxf(row[c], 0.f) * d_scale[c] + d_shift[c];
        y0  += v * lin3W[c * 2];
        y1v += v * lin3W[c * 2 + 1];
        h0  += v * con3W[c * 2];
        h1v += v * con3W[c * 2 + 1];
    }
    #pragma unroll
    for (int off = 16; off > 0; off >>= 1) {
        y0  += __shfl_xor_sync(0xffffffff, y0,  off);
        y1v += __shfl_xor_sync(0xffffffff, y1v, off);
        h0  += __shfl_xor_sync(0xffffffff, h0,  off);
        h1v += __shfl_xor_sync(0xffffffff, h1v, off);
    }
    if (lane == 0) {
        out[warp * 2]     = y0  + lin3b[0] + con3b[0];
        out[warp * 2 + 1] = y1v + lin3b[1] + con3b[1];
        d_h3[warp] = make_float2(h0, h1v);
        d_als3[warp] = h0 * asrc[0] + h1v * asrc[1];
        d_ald3[warp] = h0 * adst[0] + h1v * adst[1];
    }
}

// ---------------- layer-2 GAT: fully fused per dst (warp/dst, no atomics) ----------------
__global__ void gat_l2(float* __restrict__ out) {
    int d = (blockIdx.x * blockDim.x + threadIdx.x) >> 5;
    int lane = threadIdx.x & 31;
    if (d >= NN) return;
    int b = d_rowptr[d], e = d_rowptr[d + 1];
    float ald = d_ald3[d];
    float den = 0.f, m0 = 0.f, m1 = 0.f;
    for (int j = b + lane; j < e; j += 32) {
        int src = d_csr_src[j];
        float ex = __expf(lrelu(d_als3[src] + ald));
        float2 h = d_h3[src];
        den += ex; m0 += ex * h.x; m1 += ex * h.y;
    }
    #pragma unroll
    for (int off = 16; off > 0; off >>= 1) {
        den += __shfl_xor_sync(0xffffffff, den, off);
        m0  += __shfl_xor_sync(0xffffffff, m0,  off);
        m1  += __shfl_xor_sync(0xffffffff, m1,  off);
    }
    if (lane == 0) {
        float r = 1.f / (den + 1e-16f);
        out[d * 2]     += m0 * r;
        out[d * 2 + 1] += m1 * r;
    }
}

__global__ void relu_k(float* __restrict__ p, int n) {
    int i = blockIdx.x * blockDim.x + threadIdx.x;
    if (i < n) p[i] = fmaxf(p[i], 0.f);
}

// ---------------- launch ----------------
extern "C" void kernel_launch(void* const* d_in, const int* in_sizes, int n_in,
                              void* d_out, int out_size) {
    const float* x         = (const float*)d_in[0];
    const int*   ei        = (const int*)d_in[1];
    const float* bn1_g     = (const float*)d_in[2];
    const float* bn1_b     = (const float*)d_in[3];
    const float* lin1_W    = (const float*)d_in[4];
    const float* lin1_b    = (const float*)d_in[5];
    const float* con1_W    = (const float*)d_in[6];
    const float* con1_asrc = (const float*)d_in[7];
    const float* con1_adst = (const float*)d_in[8];
    const float* con1_b    = (const float*)d_in[9];
    const float* bn3_g     = (const float*)d_in[10];
    const float* bn3_b     = (const float*)d_in[11];
    const float* lin3_W    = (const float*)d_in[12];
    const float* lin3_b    = (const float*)d_in[13];
    const float* con3_W    = (const float*)d_in[14];
    const float* con3_asrc = (const float*)d_in[15];
    const float* con3_adst = (const float*)d_in[16];
    const float* con3_b    = (const float*)d_in[17];
    float* out = (float*)d_out;

    const int NCHUNK = (NN + 1 + 1023) / 1024;   // 49

    zero_all<<<(NN + 1 + 255) / 256, 256>>>();

    // CSR build
    hist_k<<<(EE + 255) / 256, 256>>>(ei);
    scan1_k<<<NCHUNK, 1024>>>();
    scan2_k<<<1, 64>>>(NCHUNK);
    scan3_k<<<NCHUNK - 1, 1024>>>();
    cursor_k<<<(NN + 255) / 256, 256>>>();
    scatter_k<<<(EE + 255) / 256, 256>>>(ei);

    // weights -> transposed bf16 hi/lo (independent of BN)
    wtconv<<<512, 256>>>(lin1_W, con1_W);

    // BN1 stats, then BN + hi/lo conversion of A
    bn_stats<<<512, 256>>>(x, 0);
    bn_finalize<<<1, 256>>>(bn1_g, bn1_b);
    bnconv<<<(NN * 64 + 255) / 256, 256>>>(x);

    // tensor-core dual GEMM
    gemm_bf16<<<dim3((NN + 127) / 128, 4), 256>>>(lin1_b, con1_b);

    // GAT1 (atomic-free via CSR)
    compute_al<<<(NN + 7) / 8, 256>>>(con1_asrc, con1_adst);
    attn_l1<<<(NN + 7) / 8, 256>>>();
    msg_l1<<<NN, 256>>>();

    // BN3 stats (relu fused into read)
    zero_bn<<<1, 256>>>();
    bn_stats<<<512, 256>>>(nullptr, 1);
    bn_finalize<<<1, 256>>>(bn3_g, bn3_b);

    // layer 2
    layer2_row<<<(NN + 7) / 8, 256>>>(lin3_W, lin3_b, con3_W, con3_asrc, con3_adst, con3_b, out);
    gat_l2<<<(NN + 7) / 8, 256>>>(out);
    relu_k<<<(NN * 2 + 255) / 256, 256>>>(out, NN * 2);
}

// round 6
// speedup vs baseline: 2.9555x; 1.0220x over previous
#include <cuda_runtime.h>
#include <cuda_bf16.h>
#include <cstdint>

#define NN 50000
#define EE 800000
#define FDIM 256
#define HEADS 4
#define HID 64

// ---------------- scratch (static device globals; allocation-free) ----------------
__device__ float  d_y1[NN * FDIM];     // linear1 output + GAT1 aggregation -> x1
__device__ float  d_h1[NN * FDIM];     // GAT1 transformed features
__device__ __nv_bfloat16 d_a_hi[NN * FDIM];   // BN(x) in bf16 hi
__device__ __nv_bfloat16 d_a_lo[NN * FDIM];   // residual lo
__device__ __nv_bfloat16 d_w_hi[2 * FDIM * FDIM];  // [mat][n][k] transposed weights
__device__ __nv_bfloat16 d_w_lo[2 * FDIM * FDIM];
__device__ float4 d_als1[NN];
__device__ float4 d_ald1[NN];
__device__ float2 d_h3[NN];
__device__ float  d_als3[NN];
__device__ float  d_ald3[NN];
__device__ float  d_bnsum[FDIM];
__device__ float  d_bnsumsq[FDIM];
__device__ float  d_scale[FDIM];
__device__ float  d_shift[FDIM];
__device__ int d_rowptr[NN + 1];
__device__ int d_cursor[NN];
__device__ int d_csr_src[EE];
__device__ int d_chunksum[64];

__device__ __forceinline__ float lrelu(float x) { return x > 0.f ? x : 0.2f * x; }

// ---------------- zeroing ----------------
__global__ void zero_all() {
    int i = blockIdx.x * blockDim.x + threadIdx.x;
    if (i < NN + 1) d_rowptr[i] = 0;
    if (i < FDIM) { d_bnsum[i] = 0.f; d_bnsumsq[i] = 0.f; }
}
__global__ void zero_bn() {
    d_bnsum[threadIdx.x] = 0.f;
    d_bnsumsq[threadIdx.x] = 0.f;
}

// ---------------- CSR build ----------------
__global__ void hist_k(const int* __restrict__ ei) {
    int e = blockIdx.x * blockDim.x + threadIdx.x;
    if (e < EE) atomicAdd(&d_rowptr[ei[EE + e] + 1], 1);
}
__global__ void scan1_k() {
    __shared__ int s[1024];
    int tid = threadIdx.x;
    int i = blockIdx.x * 1024 + tid;
    int v = (i <= NN) ? d_rowptr[i] : 0;
    s[tid] = v;
    __syncthreads();
    #pragma unroll
    for (int off = 1; off < 1024; off <<= 1) {
        int add = (tid >= off) ? s[tid - off] : 0;
        __syncthreads();
        s[tid] += add;
        __syncthreads();
    }
    if (i <= NN) d_rowptr[i] = s[tid];
    if (tid == 1023) d_chunksum[blockIdx.x] = s[1023];
}
__global__ void scan2_k(int nchunks) {
    __shared__ int s[64];
    int tid = threadIdx.x;
    int v = (tid < nchunks) ? d_chunksum[tid] : 0;
    s[tid] = v;
    __syncthreads();
    #pragma unroll
    for (int off = 1; off < 64; off <<= 1) {
        int add = (tid >= off) ? s[tid - off] : 0;
        __syncthreads();
        s[tid] += add;
        __syncthreads();
    }
    d_chunksum[tid] = s[tid];
}
__global__ void scan3_k() {
    int chunk = blockIdx.x + 1;
    int i = chunk * 1024 + threadIdx.x;
    if (i <= NN) d_rowptr[i] += d_chunksum[chunk - 1];
}
__global__ void cursor_k() {
    int i = blockIdx.x * blockDim.x + threadIdx.x;
    if (i < NN) d_cursor[i] = d_rowptr[i];
}
__global__ void scatter_k(const int* __restrict__ ei) {
    int e = blockIdx.x * blockDim.x + threadIdx.x;
    if (e >= EE) return;
    int s = ei[e], t = ei[EE + e];
    int pos = atomicAdd(&d_cursor[t], 1);
    d_csr_src[pos] = s;
}

// ---------------- batchnorm stats ----------------
__global__ void bn_stats(const float* __restrict__ x, int dorelu) {
    const float* src = x ? x : (const float*)d_y1;
    int c = threadIdx.x;
    float s = 0.f, s2 = 0.f;
    for (int r = blockIdx.x; r < NN; r += gridDim.x) {
        float v = src[r * FDIM + c];
        if (dorelu) v = fmaxf(v, 0.f);
        s += v; s2 += v * v;
    }
    atomicAdd(&d_bnsum[c], s);
    atomicAdd(&d_bnsumsq[c], s2);
}
__global__ void bn_finalize(const float* __restrict__ g, const float* __restrict__ b) {
    int c = threadIdx.x;
    const float invn = 1.0f / (float)NN;
    float mu = d_bnsum[c] * invn;
    float var = d_bnsumsq[c] * invn - mu * mu;
    float rs = rsqrtf(var + 1e-5f);
    float sc = rs * g[c];
    d_scale[c] = sc;
    d_shift[c] = b[c] - mu * sc;
}

// ---------------- BN + bf16 hi/lo conversion of A ----------------
__global__ void bnconv(const float* __restrict__ x) {
    int i = blockIdx.x * blockDim.x + threadIdx.x;
    if (i >= NN * 64) return;
    int c = (i & 63) << 2;
    float4 v = ((const float4*)x)[i];
    float4 sc = *(const float4*)&d_scale[c];
    float4 sh = *(const float4*)&d_shift[c];
    float a0 = v.x * sc.x + sh.x, a1 = v.y * sc.y + sh.y;
    float a2 = v.z * sc.z + sh.z, a3 = v.w * sc.w + sh.w;
    __nv_bfloat16 h0 = __float2bfloat16_rn(a0), h1 = __float2bfloat16_rn(a1);
    __nv_bfloat16 h2 = __float2bfloat16_rn(a2), h3 = __float2bfloat16_rn(a3);
    __nv_bfloat162* ph = (__nv_bfloat162*)d_a_hi;
    ph[i * 2]     = __nv_bfloat162(h0, h1);
    ph[i * 2 + 1] = __nv_bfloat162(h2, h3);
    __nv_bfloat162* pl = (__nv_bfloat162*)d_a_lo;
    pl[i * 2]     = __nv_bfloat162(__float2bfloat16_rn(a0 - __bfloat162float(h0)),
                                   __float2bfloat16_rn(a1 - __bfloat162float(h1)));
    pl[i * 2 + 1] = __nv_bfloat162(__float2bfloat16_rn(a2 - __bfloat162float(h2)),
                                   __float2bfloat16_rn(a3 - __bfloat162float(h3)));
}

// ---------------- weight transpose + hi/lo conversion: W[k][n] -> Wt[n][k] ----------------
__global__ void wtconv(const float* __restrict__ W0, const float* __restrict__ W1) {
    int i = blockIdx.x * blockDim.x + threadIdx.x;
    if (i >= 2 * 65536) return;
    int mat = i >> 16, r = i & 65535;
    int n = r >> 8, k = r & 255;
    const float* W = mat ? W1 : W0;
    float v = W[k * 256 + n];
    __nv_bfloat16 h = __float2bfloat16_rn(v);
    d_w_hi[i] = h;
    d_w_lo[i] = __float2bfloat16_rn(v - __bfloat162float(h));
}

// ---------------- bf16 split tensor-core GEMM (cp.async double-buffered) ----------------
#define SLDA 40
#define APLANE (128 * SLDA * 2)       // bytes per plane (10240)
#define ABUF (2 * APLANE)             // A region per stage (hi+lo)
#define STAGEB (2 * ABUF)             // per-stage bytes A+B (40960)

__device__ __forceinline__ void mma16816(float* d, const uint32_t* a, uint32_t b0, uint32_t b1) {
    asm volatile("mma.sync.aligned.m16n8k16.row.col.f32.bf16.bf16.f32 "
                 "{%0,%1,%2,%3}, {%4,%5,%6,%7}, {%8,%9}, {%0,%1,%2,%3};"
                 : "+f"(d[0]), "+f"(d[1]), "+f"(d[2]), "+f"(d[3])
                 : "r"(a[0]), "r"(a[1]), "r"(a[2]), "r"(a[3]), "r"(b0), "r"(b1));
}
__device__ __forceinline__ void ldsm4(uint32_t* r, uint32_t addr) {
    asm volatile("ldmatrix.sync.aligned.m8n8.x4.shared.b16 {%0,%1,%2,%3}, [%4];"
                 : "=r"(r[0]), "=r"(r[1]), "=r"(r[2]), "=r"(r[3]) : "r"(addr));
}
__device__ __forceinline__ void cpa16(uint32_t saddr, const void* gaddr, int bytes) {
    asm volatile("cp.async.cg.shared.global [%0], [%1], 16, %2;"
                 :: "r"(saddr), "l"(gaddr), "r"(bytes));
}

extern __shared__ char dynsmem[];

__global__ void __launch_bounds__(256, 2)
gemm_bf16(const float* __restrict__ b0a, const float* __restrict__ b0b) {
    int t = threadIdx.x;
    int m0 = blockIdx.x * 128;
    int mat = blockIdx.y >> 1;
    int n0 = (blockIdx.y & 1) * 128;
    const __nv_bfloat16* Bh = d_w_hi + mat * 65536;
    const __nv_bfloat16* Bl = d_w_lo + mat * 65536;
    float* C = mat ? d_h1 : d_y1;

    int lrow = t >> 1, seg = t & 1;
    int gm = m0 + lrow;
    bool aok = gm < NN;
    int gmc = aok ? gm : 0;
    int abytes = aok ? 16 : 0;

    const char* gAh = (const char*)(d_a_hi + (size_t)gmc * 256) + seg * 32;
    const char* gAl = (const char*)(d_a_lo + (size_t)gmc * 256) + seg * 32;
    const char* gBh = (const char*)(Bh + (size_t)(n0 + lrow) * 256) + seg * 32;
    const char* gBl = (const char*)(Bl + (size_t)(n0 + lrow) * 256) + seg * 32;

    uint32_t smem0 = (uint32_t)__cvta_generic_to_shared(dynsmem);
    uint32_t rowoff = (uint32_t)(lrow * (SLDA * 2) + seg * 32);

    // issue loads for k-slab `slab` into stage `st`
    auto issue = [&](int slab, int st) {
        uint32_t base = smem0 + st * STAGEB;
        int go = slab * 64;   // 32 k-elems * 2B per row
        uint32_t sa = base + rowoff;
        cpa16(sa,               gAh + go,      abytes);
        cpa16(sa + 16,          gAh + go + 16, abytes);
        cpa16(sa + APLANE,      gAl + go,      abytes);
        cpa16(sa + APLANE + 16, gAl + go + 16, abytes);
        uint32_t sb = base + ABUF + rowoff;
        cpa16(sb,               gBh + go,      16);
        cpa16(sb + 16,          gBh + go + 16, 16);
        cpa16(sb + APLANE,      gBl + go,      16);
        cpa16(sb + APLANE + 16, gBl + go + 16, 16);
        asm volatile("cp.async.commit_group;");
    };

    issue(0, 0);
    issue(1, 1);

    int wid = t >> 5, lane = t & 31;
    int wm0 = (wid & 1) * 64, wn0 = (wid >> 1) * 32;
    float acc[4][4][4] = {};

    int a_r = (lane & 15);
    int a_c = (lane >> 4) << 3;
    int b_r = (lane & 7) + ((lane & 16) ? 8 : 0);
    int b_c = (lane & 8) ? 8 : 0;

    for (int s = 0; s < 8; s++) {
        if (s < 7) asm volatile("cp.async.wait_group 1;");
        else       asm volatile("cp.async.wait_group 0;");
        __syncthreads();
        uint32_t sAu = smem0 + (s & 1) * STAGEB;
        uint32_t sBu = sAu + ABUF;
        #pragma unroll
        for (int kk = 0; kk < 32; kk += 16) {
            uint32_t bh[2][4], bl[2][4];
            #pragma unroll
            for (int jp = 0; jp < 2; jp++) {
                uint32_t addr = sBu + (uint32_t)(((wn0 + jp * 16 + b_r) * SLDA + kk + b_c) * 2);
                ldsm4(bh[jp], addr);
                ldsm4(bl[jp], addr + APLANE);
            }
            #pragma unroll
            for (int i = 0; i < 4; i++) {
                uint32_t ah[4], al[4];
                uint32_t addr = sAu + (uint32_t)(((wm0 + i * 16 + a_r) * SLDA + kk + a_c) * 2);
                ldsm4(ah, addr);
                ldsm4(al, addr + APLANE);
                #pragma unroll
                for (int j = 0; j < 4; j++) {
                    int jp = j >> 1, o = (j & 1) * 2;
                    mma16816(acc[i][j], ah, bh[jp][o], bh[jp][o + 1]);
                    mma16816(acc[i][j], ah, bl[jp][o], bl[jp][o + 1]);
                    mma16816(acc[i][j], al, bh[jp][o], bh[jp][o + 1]);
                }
            }
        }
        __syncthreads();
        if (s + 2 < 8) issue(s + 2, s & 1);
    }

    int g = lane >> 2, tq = lane & 3;
    #pragma unroll
    for (int j = 0; j < 4; j++) {
        int gcol = n0 + wn0 + j * 8 + tq * 2;
        float bx = 0.f, by = 0.f;
        if (!mat) {
            bx = b0a[gcol] + b0b[gcol];
            by = b0a[gcol + 1] + b0b[gcol + 1];
        }
        #pragma unroll
        for (int i = 0; i < 4; i++) {
            int r0 = m0 + wm0 + i * 16 + g;
            if (r0 < NN)
                *(float2*)&C[(size_t)r0 * 256 + gcol] =
                    make_float2(acc[i][j][0] + bx, acc[i][j][1] + by);
            int r1 = r0 + 8;
            if (r1 < NN)
                *(float2*)&C[(size_t)r1 * 256 + gcol] =
                    make_float2(acc[i][j][2] + bx, acc[i][j][3] + by);
        }
    }
}

// ---------------- attention logit contributions (layer 1) ----------------
__global__ void compute_al(const float* __restrict__ asrc, const float* __restrict__ adst) {
    int warp = (blockIdx.x * blockDim.x + threadIdx.x) >> 5;
    int lane = threadIdx.x & 31;
    if (warp >= NN) return;
    const float4* hr = (const float4*)&d_h1[(size_t)warp * 256];
    int head = lane >> 3;
    float s = 0.f, d = 0.f;
    #pragma unroll
    for (int q = 0; q < 2; q++) {
        float4 hv = hr[lane * 2 + q];
        int cbase = (lane * 8 + q * 4) & 63;
        const float* as = asrc + head * 64 + cbase;
        const float* ad = adst + head * 64 + cbase;
        s += hv.x * as[0] + hv.y * as[1] + hv.z * as[2] + hv.w * as[3];
        d += hv.x * ad[0] + hv.y * ad[1] + hv.z * ad[2] + hv.w * ad[3];
    }
    #pragma unroll
    for (int off = 4; off > 0; off >>= 1) {
        s += __shfl_down_sync(0xffffffff, s, off);
        d += __shfl_down_sync(0xffffffff, d, off);
    }
    if ((lane & 7) == 0) {
        ((float*)&d_als1[warp])[head] = s;
        ((float*)&d_ald1[warp])[head] = d;
    }
}

// ---------------- fused layer-1 GAT: softmax + aggregation, deferred division ----------------
__global__ void gat1_fused() {
    int d = blockIdx.x;
    int t = threadIdx.x;
    int b = d_rowptr[d], e = d_rowptr[d + 1];
    if (b == e) return;
    __shared__ int   s_src[64];
    __shared__ float s_ex[64 * 4];
    __shared__ float s_rden[4];
    float4 ald = d_ald1[d];
    float dx = 0.f, dy = 0.f, dz = 0.f, dw = 0.f;   // per-thread (t<64) denom partials
    int h = t >> 6;
    float acc = 0.f;
    const float* __restrict__ hp = (const float*)d_h1;
    for (int c0 = b; c0 < e; c0 += 64) {
        int cnt = min(64, e - c0);
        __syncthreads();
        if (t < cnt) {
            int src = d_csr_src[c0 + t];
            s_src[t] = src;
            float4 a = d_als1[src];
            float ex0 = __expf(lrelu(a.x + ald.x));
            float ex1 = __expf(lrelu(a.y + ald.y));
            float ex2 = __expf(lrelu(a.z + ald.z));
            float ex3 = __expf(lrelu(a.w + ald.w));
            s_ex[t * 4 + 0] = ex0; s_ex[t * 4 + 1] = ex1;
            s_ex[t * 4 + 2] = ex2; s_ex[t * 4 + 3] = ex3;
            dx += ex0; dy += ex1; dz += ex2; dw += ex3;
        }
        __syncthreads();
        #pragma unroll 4
        for (int j = 0; j < cnt; j++) {
            acc += s_ex[j * 4 + h] * hp[(size_t)s_src[j] * 256 + t];
        }
    }
    // denominator reduction (t<64 hold partials)
    __syncthreads();
    if (t < 64) {
        s_ex[t * 4 + 0] = dx; s_ex[t * 4 + 1] = dy;
        s_ex[t * 4 + 2] = dz; s_ex[t * 4 + 3] = dw;
    }
    __syncthreads();
    if (t < 4) {
        float s = 0.f;
        #pragma unroll 8
        for (int j = 0; j < 64; j++) s += s_ex[j * 4 + t];
        s_rden[t] = 1.f / (s + 1e-16f);
    }
    __syncthreads();
    d_y1[(size_t)d * 256 + t] += acc * s_rden[h];
}

// ---------------- layer 2: fused relu+BN + linear3 + GAT2 features/logits ----------------
__global__ void layer2_row(const float* __restrict__ lin3W, const float* __restrict__ lin3b,
                           const float* __restrict__ con3W, const float* __restrict__ asrc,
                           const float* __restrict__ adst, const float* __restrict__ con3b,
                           float* __restrict__ out) {
    int warp = (blockIdx.x * blockDim.x + threadIdx.x) >> 5;
    int lane = threadIdx.x & 31;
    if (warp >= NN) return;
    const float* row = (const float*)d_y1 + (size_t)warp * 256;
    float y0 = 0.f, y1v = 0.f, h0 = 0.f, h1v = 0.f;
    #pragma unroll
    for (int q = 0; q < 8; q++) {
        int c = lane + q * 32;
        float v = fmaxf(row[c], 0.f) * d_scale[c] + d_shift[c];
        y0  += v * lin3W[c * 2];
        y1v += v * lin3W[c * 2 + 1];
        h0  += v * con3W[c * 2];
        h1v += v * con3W[c * 2 + 1];
    }
    #pragma unroll
    for (int off = 16; off > 0; off >>= 1) {
        y0  += __shfl_xor_sync(0xffffffff, y0,  off);
        y1v += __shfl_xor_sync(0xffffffff, y1v, off);
        h0  += __shfl_xor_sync(0xffffffff, h0,  off);
        h1v += __shfl_xor_sync(0xffffffff, h1v, off);
    }
    if (lane == 0) {
        out[warp * 2]     = y0  + lin3b[0] + con3b[0];
        out[warp * 2 + 1] = y1v + lin3b[1] + con3b[1];
        d_h3[warp] = make_float2(h0, h1v);
        d_als3[warp] = h0 * asrc[0] + h1v * asrc[1];
        d_ald3[warp] = h0 * adst[0] + h1v * adst[1];
    }
}

// ---------------- layer-2 GAT + final relu (warp/dst, no atomics) ----------------
__global__ void gat_l2(float* __restrict__ out) {
    int d = (blockIdx.x * blockDim.x + threadIdx.x) >> 5;
    int lane = threadIdx.x & 31;
    if (d >= NN) return;
    int b = d_rowptr[d], e = d_rowptr[d + 1];
    float ald = d_ald3[d];
    float den = 0.f, m0 = 0.f, m1 = 0.f;
    for (int j = b + lane; j < e; j += 32) {
        int src = d_csr_src[j];
        float ex = __expf(lrelu(d_als3[src] + ald));
        float2 h = d_h3[src];
        den += ex; m0 += ex * h.x; m1 += ex * h.y;
    }
    #pragma unroll
    for (int off = 16; off > 0; off >>= 1) {
        den += __shfl_xor_sync(0xffffffff, den, off);
        m0  += __shfl_xor_sync(0xffffffff, m0,  off);
        m1  += __shfl_xor_sync(0xffffffff, m1,  off);
    }
    if (lane == 0) {
        float r = 1.f / (den + 1e-16f);
        out[d * 2]     = fmaxf(out[d * 2]     + m0 * r, 0.f);
        out[d * 2 + 1] = fmaxf(out[d * 2 + 1] + m1 * r, 0.f);
    }
}

// ---------------- launch ----------------
extern "C" void kernel_launch(void* const* d_in, const int* in_sizes, int n_in,
                              void* d_out, int out_size) {
    const float* x         = (const float*)d_in[0];
    const int*   ei        = (const int*)d_in[1];
    const float* bn1_g     = (const float*)d_in[2];
    const float* bn1_b     = (const float*)d_in[3];
    const float* lin1_W    = (const float*)d_in[4];
    const float* lin1_b    = (const float*)d_in[5];
    const float* con1_W    = (const float*)d_in[6];
    const float* con1_asrc = (const float*)d_in[7];
    const float* con1_adst = (const float*)d_in[8];
    const float* con1_b    = (const float*)d_in[9];
    const float* bn3_g     = (const float*)d_in[10];
    const float* bn3_b     = (const float*)d_in[11];
    const float* lin3_W    = (const float*)d_in[12];
    const float* lin3_b    = (const float*)d_in[13];
    const float* con3_W    = (const float*)d_in[14];
    const float* con3_asrc = (const float*)d_in[15];
    const float* con3_adst = (const float*)d_in[16];
    const float* con3_b    = (const float*)d_in[17];
    float* out = (float*)d_out;

    const int NCHUNK = (NN + 1 + 1023) / 1024;   // 49
    const int GSMEM = 2 * STAGEB;                // 81920 bytes

    // host-side immediate call (not a stream op; safe under graph capture)
    cudaFuncSetAttribute(gemm_bf16, cudaFuncAttributeMaxDynamicSharedMemorySize, GSMEM);

    zero_all<<<(NN + 1 + 255) / 256, 256>>>();

    // CSR build
    hist_k<<<(EE + 255) / 256, 256>>>(ei);
    scan1_k<<<NCHUNK, 1024>>>();
    scan2_k<<<1, 64>>>(NCHUNK);
    scan3_k<<<NCHUNK - 1, 1024>>>();
    cursor_k<<<(NN + 255) / 256, 256>>>();
    scatter_k<<<(EE + 255) / 256, 256>>>(ei);

    // weights -> transposed bf16 hi/lo
    wtconv<<<512, 256>>>(lin1_W, con1_W);

    // BN1 stats, then BN + hi/lo conversion of A
    bn_stats<<<512, 256>>>(x, 0);
    bn_finalize<<<1, 256>>>(bn1_g, bn1_b);
    bnconv<<<(NN * 64 + 255) / 256, 256>>>(x);

    // tensor-core dual GEMM (cp.async pipelined)
    gemm_bf16<<<dim3((NN + 127) / 128, 4), 256, GSMEM>>>(lin1_b, con1_b);

    // GAT1: logits then fused softmax+aggregate (atomic-free, deferred division)
    compute_al<<<(NN + 7) / 8, 256>>>(con1_asrc, con1_adst);
    gat1_fused<<<NN, 256>>>();

    // BN3 stats (relu fused into read)
    zero_bn<<<1, 256>>>();
    bn_stats<<<512, 256>>>(nullptr, 1);
    bn_finalize<<<1, 256>>>(bn3_g, bn3_b);

    // layer 2
    layer2_row<<<(NN + 7) / 8, 256>>>(lin3_W, lin3_b, con3_W, con3_asrc, con3_adst, con3_b, out);
    gat_l2<<<(NN + 7) / 8, 256>>>(out);
}

// round 8
// speedup vs baseline: 3.1372x; 1.0615x over previous
#include <cuda_runtime.h>
#include <cuda_bf16.h>
#include <cstdint>

#define NN 50000
#define EE 800000
#define FDIM 256
#define HEADS 4
#define HID 64
#define BNPART 256

// ---------------- scratch (static device globals; allocation-free) ----------------
__device__ float  d_y1[NN * FDIM];     // linear1 output + GAT1 aggregation -> x1
__device__ float  d_h1[NN * FDIM];     // GAT1 transformed features
__device__ __nv_bfloat16 d_a_hi[NN * FDIM];   // BN(x) in bf16 hi
__device__ __nv_bfloat16 d_a_lo[NN * FDIM];   // residual lo
__device__ __nv_bfloat16 d_w_hi[2 * FDIM * FDIM];  // [mat][n][k] transposed weights
__device__ __nv_bfloat16 d_w_lo[2 * FDIM * FDIM];
__device__ float4 d_als1[NN];
__device__ float4 d_ald1[NN];
__device__ float2 d_h3[NN];
__device__ float  d_als3[NN];
__device__ float  d_ald3[NN];
__device__ float  d_bnps[BNPART * FDIM];   // BN partial sums (no atomics, no zeroing)
__device__ float  d_bnpq[BNPART * FDIM];
__device__ float  d_scale[FDIM];
__device__ float  d_shift[FDIM];
__device__ int d_rowptr[NN + 1];
__device__ int d_cursor[NN];
__device__ int d_csr_src[EE];
__device__ int d_chunksum[64];

__device__ __forceinline__ float lrelu(float x) { return x > 0.f ? x : 0.2f * x; }

// ---------------- BN stats: per-block partials (no atomics, no pre-zero) ----------------
__global__ void bn_stats(const float* __restrict__ x, int dorelu) {
    const float* src = x ? x : (const float*)d_y1;
    int c = threadIdx.x;
    float s = 0.f, s2 = 0.f;
    for (int r = blockIdx.x; r < NN; r += BNPART) {
        float v = src[r * FDIM + c];
        if (dorelu) v = fmaxf(v, 0.f);
        s += v; s2 += v * v;
    }
    d_bnps[blockIdx.x * FDIM + c] = s;
    d_bnpq[blockIdx.x * FDIM + c] = s2;
}
__global__ void bn_finalize(const float* __restrict__ g, const float* __restrict__ b) {
    int c = threadIdx.x;
    float s = 0.f, q = 0.f;
    #pragma unroll 8
    for (int i = 0; i < BNPART; i++) {
        s += d_bnps[i * FDIM + c];
        q += d_bnpq[i * FDIM + c];
    }
    const float invn = 1.0f / (float)NN;
    float mu = s * invn;
    float var = q * invn - mu * mu;
    float rs = rsqrtf(var + 1e-5f);
    float sc = rs * g[c];
    d_scale[c] = sc;
    d_shift[c] = b[c] - mu * sc;
}

// ---------------- prep: BN+hi/lo conv of A, weight transpose+conv, rowptr zero ----------------
#define PREP_A 12500                   // NN*64 float4 / 256
#define PREP_W 512                     // 2*65536 / 256
#define PREP_Z 196                     // (NN+1+255)/256
__global__ void prep_k(const float* __restrict__ x,
                       const float* __restrict__ W0, const float* __restrict__ W1) {
    int bid = blockIdx.x;
    int t = threadIdx.x;
    if (bid < PREP_A) {
        int i = bid * 256 + t;
        int c = (i & 63) << 2;
        float4 v = ((const float4*)x)[i];
        float4 sc = *(const float4*)&d_scale[c];
        float4 sh = *(const float4*)&d_shift[c];
        float a0 = v.x * sc.x + sh.x, a1 = v.y * sc.y + sh.y;
        float a2 = v.z * sc.z + sh.z, a3 = v.w * sc.w + sh.w;
        __nv_bfloat16 h0 = __float2bfloat16_rn(a0), h1 = __float2bfloat16_rn(a1);
        __nv_bfloat16 h2 = __float2bfloat16_rn(a2), h3 = __float2bfloat16_rn(a3);
        __nv_bfloat162* ph = (__nv_bfloat162*)d_a_hi;
        ph[i * 2]     = __nv_bfloat162(h0, h1);
        ph[i * 2 + 1] = __nv_bfloat162(h2, h3);
        __nv_bfloat162* pl = (__nv_bfloat162*)d_a_lo;
        pl[i * 2]     = __nv_bfloat162(__float2bfloat16_rn(a0 - __bfloat162float(h0)),
                                       __float2bfloat16_rn(a1 - __bfloat162float(h1)));
        pl[i * 2 + 1] = __nv_bfloat162(__float2bfloat16_rn(a2 - __bfloat162float(h2)),
                                       __float2bfloat16_rn(a3 - __bfloat162float(h3)));
    } else if (bid < PREP_A + PREP_W) {
        int i = (bid - PREP_A) * 256 + t;
        int mat = i >> 16, r = i & 65535;
        int n = r >> 8, k = r & 255;
        const float* W = mat ? W1 : W0;
        float v = W[k * 256 + n];
        __nv_bfloat16 h = __float2bfloat16_rn(v);
        d_w_hi[i] = h;
        d_w_lo[i] = __float2bfloat16_rn(v - __bfloat162float(h));
    } else {
        int i = (bid - PREP_A - PREP_W) * 256 + t;
        if (i <= NN) d_rowptr[i] = 0;
    }
}

// ---------------- CSR build ----------------
__global__ void hist_k(const int* __restrict__ ei) {
    int e = blockIdx.x * blockDim.x + threadIdx.x;
    if (e < EE) atomicAdd(&d_rowptr[ei[EE + e] + 1], 1);
}
__global__ void scan1_k() {
    __shared__ int s[1024];
    int tid = threadIdx.x;
    int i = blockIdx.x * 1024 + tid;
    int v = (i <= NN) ? d_rowptr[i] : 0;
    s[tid] = v;
    __syncthreads();
    #pragma unroll
    for (int off = 1; off < 1024; off <<= 1) {
        int add = (tid >= off) ? s[tid - off] : 0;
        __syncthreads();
        s[tid] += add;
        __syncthreads();
    }
    if (i <= NN) d_rowptr[i] = s[tid];
    if (tid == 1023) d_chunksum[blockIdx.x] = s[1023];
}
__global__ void scan2_k(int nchunks) {
    __shared__ int s[64];
    int tid = threadIdx.x;
    int v = (tid < nchunks) ? d_chunksum[tid] : 0;
    s[tid] = v;
    __syncthreads();
    #pragma unroll
    for (int off = 1; off < 64; off <<= 1) {
        int add = (tid >= off) ? s[tid - off] : 0;
        __syncthreads();
        s[tid] += add;
        __syncthreads();
    }
    d_chunksum[tid] = s[tid];
}
__global__ void scan3_k() {
    int chunk = blockIdx.x + 1;
    int i = chunk * 1024 + threadIdx.x;
    if (i <= NN) d_rowptr[i] += d_chunksum[chunk - 1];
}
__global__ void cursor_k() {
    int i = blockIdx.x * blockDim.x + threadIdx.x;
    if (i < NN) d_cursor[i] = d_rowptr[i];
}
__global__ void scatter_k(const int* __restrict__ ei) {
    int e = blockIdx.x * blockDim.x + threadIdx.x;
    if (e >= EE) return;
    int s = ei[e], t = ei[EE + e];
    int pos = atomicAdd(&d_cursor[t], 1);
    d_csr_src[pos] = s;
}

// ---------------- bf16 split tensor-core GEMM (cp.async double-buffered) ----------------
#define SLDA 40
#define APLANE (128 * SLDA * 2)       // bytes per plane (10240)
#define ABUF (2 * APLANE)             // A region per stage (hi+lo)
#define STAGEB (2 * ABUF)             // per-stage bytes A+B (40960)

__device__ __forceinline__ void mma16816(float* d, const uint32_t* a, uint32_t b0, uint32_t b1) {
    asm volatile("mma.sync.aligned.m16n8k16.row.col.f32.bf16.bf16.f32 "
                 "{%0,%1,%2,%3}, {%4,%5,%6,%7}, {%8,%9}, {%0,%1,%2,%3};"
                 : "+f"(d[0]), "+f"(d[1]), "+f"(d[2]), "+f"(d[3])
                 : "r"(a[0]), "r"(a[1]), "r"(a[2]), "r"(a[3]), "r"(b0), "r"(b1));
}
__device__ __forceinline__ void ldsm4(uint32_t* r, uint32_t addr) {
    asm volatile("ldmatrix.sync.aligned.m8n8.x4.shared.b16 {%0,%1,%2,%3}, [%4];"
                 : "=r"(r[0]), "=r"(r[1]), "=r"(r[2]), "=r"(r[3]) : "r"(addr));
}
__device__ __forceinline__ void cpa16(uint32_t saddr, const void* gaddr, int bytes) {
    asm volatile("cp.async.cg.shared.global [%0], [%1], 16, %2;"
                 :: "r"(saddr), "l"(gaddr), "r"(bytes));
}

extern __shared__ char dynsmem[];

__global__ void __launch_bounds__(256, 2)
gemm_bf16(const float* __restrict__ b0a, const float* __restrict__ b0b) {
    int t = threadIdx.x;
    int m0 = blockIdx.x * 128;
    int mat = blockIdx.y >> 1;
    int n0 = (blockIdx.y & 1) * 128;
    const __nv_bfloat16* Bh = d_w_hi + mat * 65536;
    const __nv_bfloat16* Bl = d_w_lo + mat * 65536;
    float* C = mat ? d_h1 : d_y1;

    int lrow = t >> 1, seg = t & 1;
    int gm = m0 + lrow;
    bool aok = gm < NN;
    int gmc = aok ? gm : 0;
    int abytes = aok ? 16 : 0;

    const char* gAh = (const char*)(d_a_hi + (size_t)gmc * 256) + seg * 32;
    const char* gAl = (const char*)(d_a_lo + (size_t)gmc * 256) + seg * 32;
    const char* gBh = (const char*)(Bh + (size_t)(n0 + lrow) * 256) + seg * 32;
    const char* gBl = (const char*)(Bl + (size_t)(n0 + lrow) * 256) + seg * 32;

    uint32_t smem0 = (uint32_t)__cvta_generic_to_shared(dynsmem);
    uint32_t rowoff = (uint32_t)(lrow * (SLDA * 2) + seg * 32);

    auto issue = [&](int slab, int st) {
        uint32_t base = smem0 + st * STAGEB;
        int go = slab * 64;
        uint32_t sa = base + rowoff;
        cpa16(sa,               gAh + go,      abytes);
        cpa16(sa + 16,          gAh + go + 16, abytes);
        cpa16(sa + APLANE,      gAl + go,      abytes);
        cpa16(sa + APLANE + 16, gAl + go + 16, abytes);
        uint32_t sbb = base + ABUF + rowoff;
        cpa16(sbb,               gBh + go,      16);
        cpa16(sbb + 16,          gBh + go + 16, 16);
        cpa16(sbb + APLANE,      gBl + go,      16);
        cpa16(sbb + APLANE + 16, gBl + go + 16, 16);
        asm volatile("cp.async.commit_group;");
    };

    issue(0, 0);
    issue(1, 1);

    int wid = t >> 5, lane = t & 31;
    int wm0 = (wid & 1) * 64, wn0 = (wid >> 1) * 32;
    float acc[4][4][4] = {};

    int a_r = (lane & 15);
    int a_c = (lane >> 4) << 3;
    int b_r = (lane & 7) + ((lane & 16) ? 8 : 0);
    int b_c = (lane & 8) ? 8 : 0;

    for (int s = 0; s < 8; s++) {
        if (s < 7) asm volatile("cp.async.wait_group 1;");
        else       asm volatile("cp.async.wait_group 0;");
        __syncthreads();
        uint32_t sAu = smem0 + (s & 1) * STAGEB;
        uint32_t sBu = sAu + ABUF;
        #pragma unroll
        for (int kk = 0; kk < 32; kk += 16) {
            uint32_t bh[2][4], bl[2][4];
            #pragma unroll
            for (int jp = 0; jp < 2; jp++) {
                uint32_t addr = sBu + (uint32_t)(((wn0 + jp * 16 + b_r) * SLDA + kk + b_c) * 2);
                ldsm4(bh[jp], addr);
                ldsm4(bl[jp], addr + APLANE);
            }
            #pragma unroll
            for (int i = 0; i < 4; i++) {
                uint32_t ah[4], al[4];
                uint32_t addr = sAu + (uint32_t)(((wm0 + i * 16 + a_r) * SLDA + kk + a_c) * 2);
                ldsm4(ah, addr);
                ldsm4(al, addr + APLANE);
                #pragma unroll
                for (int j = 0; j < 4; j++) {
                    int jp = j >> 1, o = (j & 1) * 2;
                    mma16816(acc[i][j], ah, bh[jp][o], bh[jp][o + 1]);
                    mma16816(acc[i][j], ah, bl[jp][o], bl[jp][o + 1]);
                    mma16816(acc[i][j], al, bh[jp][o], bh[jp][o + 1]);
                }
            }
        }
        __syncthreads();
        if (s + 2 < 8) issue(s + 2, s & 1);
    }

    int g = lane >> 2, tq = lane & 3;
    #pragma unroll
    for (int j = 0; j < 4; j++) {
        int gcol = n0 + wn0 + j * 8 + tq * 2;
        float bx = 0.f, by = 0.f;
        if (!mat) {
            bx = b0a[gcol] + b0b[gcol];
            by = b0a[gcol + 1] + b0b[gcol + 1];
        }
        #pragma unroll
        for (int i = 0; i < 4; i++) {
            int r0 = m0 + wm0 + i * 16 + g;
            if (r0 < NN)
                *(float2*)&C[(size_t)r0 * 256 + gcol] =
                    make_float2(acc[i][j][0] + bx, acc[i][j][1] + by);
            int r1 = r0 + 8;
            if (r1 < NN)
                *(float2*)&C[(size_t)r1 * 256 + gcol] =
                    make_float2(acc[i][j][2] + bx, acc[i][j][3] + by);
        }
    }
}

// ---------------- attention logit contributions (layer 1) ----------------
__global__ void compute_al(const float* __restrict__ asrc, const float* __restrict__ adst) {
    int warp = (blockIdx.x * blockDim.x + threadIdx.x) >> 5;
    int lane = threadIdx.x & 31;
    if (warp >= NN) return;
    const float4* hr = (const float4*)&d_h1[(size_t)warp * 256];
    int head = lane >> 3;
    float s = 0.f, d = 0.f;
    #pragma unroll
    for (int q = 0; q < 2; q++) {
        float4 hv = hr[lane * 2 + q];
        int cbase = (lane * 8 + q * 4) & 63;
        const float* as = asrc + head * 64 + cbase;
        const float* ad = adst + head * 64 + cbase;
        s += hv.x * as[0] + hv.y * as[1] + hv.z * as[2] + hv.w * as[3];
        d += hv.x * ad[0] + hv.y * ad[1] + hv.z * ad[2] + hv.w * ad[3];
    }
    #pragma unroll
    for (int off = 4; off > 0; off >>= 1) {
        s += __shfl_down_sync(0xffffffff, s, off);
        d += __shfl_down_sync(0xffffffff, d, off);
    }
    if ((lane & 7) == 0) {
        ((float*)&d_als1[warp])[head] = s;
        ((float*)&d_ald1[warp])[head] = d;
    }
}

// ---------------- fused layer-1 GAT: softmax + aggregation (float4, 4-way src) ----------------
__global__ void gat1_fused() {
    int d = blockIdx.x;
    int t = threadIdx.x;
    int b = d_rowptr[d], e = d_rowptr[d + 1];
    if (b == e) return;
    __shared__ int    s_src[64];
    __shared__ float  s_ex[64 * 4];
    __shared__ float4 s_acc[256];
    __shared__ float  s_rden[4];
    float4 ald = d_ald1[d];
    float dx = 0.f, dy = 0.f, dz = 0.f, dw = 0.f;   // denom partials (t<64 lanes)
    int cg = t & 63;        // channel group: channels cg*4..cg*4+3
    int sp = t >> 6;        // src-parallel lane 0..3
    int h = cg >> 4;        // head of this channel group
    float4 acc = make_float4(0.f, 0.f, 0.f, 0.f);
    const float* __restrict__ hp = (const float*)d_h1;
    for (int c0 = b; c0 < e; c0 += 64) {
        int cnt = min(64, e - c0);
        __syncthreads();
        if (t < cnt) {
            int src = d_csr_src[c0 + t];
            s_src[t] = src;
            float4 a = d_als1[src];
            float ex0 = __expf(lrelu(a.x + ald.x));
            float ex1 = __expf(lrelu(a.y + ald.y));
            float ex2 = __expf(lrelu(a.z + ald.z));
            float ex3 = __expf(lrelu(a.w + ald.w));
            s_ex[t * 4 + 0] = ex0; s_ex[t * 4 + 1] = ex1;
            s_ex[t * 4 + 2] = ex2; s_ex[t * 4 + 3] = ex3;
            dx += ex0; dy += ex1; dz += ex2; dw += ex3;
        }
        __syncthreads();
        for (int j = sp; j < cnt; j += 4) {
            float w = s_ex[j * 4 + h];
            float4 hv = *(const float4*)&hp[(size_t)s_src[j] * 256 + cg * 4];
            acc.x += w * hv.x; acc.y += w * hv.y;
            acc.z += w * hv.z; acc.w += w * hv.w;
        }
    }
    __syncthreads();
    s_acc[t] = acc;
    if (t < 64) {
        s_ex[t * 4 + 0] = dx; s_ex[t * 4 + 1] = dy;
        s_ex[t * 4 + 2] = dz; s_ex[t * 4 + 3] = dw;
    }
    __syncthreads();
    if (t < 4) {
        float s = 0.f;
        #pragma unroll 8
        for (int j = 0; j < 64; j++) s += s_ex[j * 4 + t];
        s_rden[t] = 1.f / (s + 1e-16f);
    }
    __syncthreads();
    if (t < 64) {
        float4 a0 = s_acc[t], a1 = s_acc[t + 64], a2 = s_acc[t + 128], a3 = s_acc[t + 192];
        float r = s_rden[h];
        float4* yp = (float4*)&d_y1[(size_t)d * 256 + t * 4];
        float4 old = *yp;
        old.x += (a0.x + a1.x + a2.x + a3.x) * r;
        old.y += (a0.y + a1.y + a2.y + a3.y) * r;
        old.z += (a0.z + a1.z + a2.z + a3.z) * r;
        old.w += (a0.w + a1.w + a2.w + a3.w) * r;
        *yp = old;
    }
}

// ---------------- layer 2: fused relu+BN + linear3 + GAT2 features/logits ----------------
__global__ void layer2_row(const float* __restrict__ lin3W, const float* __restrict__ lin3b,
                           const float* __restrict__ con3W, const float* __restrict__ asrc,
                           const float* __restrict__ adst, const float* __restrict__ con3b,
                           float* __restrict__ out) {
    int warp = (blockIdx.x * blockDim.x + threadIdx.x) >> 5;
    int lane = threadIdx.x & 31;
    if (warp >= NN) return;
    const float* row = (const float*)d_y1 + (size_t)warp * 256;
    float y0 = 0.f, y1v = 0.f, h0 = 0.f, h1v = 0.f;
    #pragma unroll
    for (int q = 0; q < 8; q++) {
        int c = lane + q * 32;
        float v = fmaxf(row[c], 0.f) * d_scale[c] + d_shift[c];
        y0  += v * lin3W[c * 2];
        y1v += v * lin3W[c * 2 + 1];
        h0  += v * con3W[c * 2];
        h1v += v * con3W[c * 2 + 1];
    }
    #pragma unroll
    for (int off = 16; off > 0; off >>= 1) {
        y0  += __shfl_xor_sync(0xffffffff, y0,  off);
        y1v += __shfl_xor_sync(0xffffffff, y1v, off);
        h0  += __shfl_xor_sync(0xffffffff, h0,  off);
        h1v += __shfl_xor_sync(0xffffffff, h1v, off);
    }
    if (lane == 0) {
        out[warp * 2]     = y0  + lin3b[0] + con3b[0];
        out[warp * 2 + 1] = y1v + lin3b[1] + con3b[1];
        d_h3[warp] = make_float2(h0, h1v);
        d_als3[warp] = h0 * asrc[0] + h1v * asrc[1];
        d_ald3[warp] = h0 * adst[0] + h1v * adst[1];
    }
}

// ---------------- layer-2 GAT + final relu (warp/dst, no atomics) ----------------
__global__ void gat_l2(float* __restrict__ out) {
    int d = (blockIdx.x * blockDim.x + threadIdx.x) >> 5;
    int lane = threadIdx.x & 31;
    if (d >= NN) return;
    int b = d_rowptr[d], e = d_rowptr[d + 1];
    float ald = d_ald3[d];
    float den = 0.f, m0 = 0.f, m1 = 0.f;
    for (int j = b + lane; j < e; j += 32) {
        int src = d_csr_src[j];
        float ex = __expf(lrelu(d_als3[src] + ald));
        float2 h = d_h3[src];
        den += ex; m0 += ex * h.x; m1 += ex * h.y;
    }
    #pragma unroll
    for (int off = 16; off > 0; off >>= 1) {
        den += __shfl_xor_sync(0xffffffff, den, off);
        m0  += __shfl_xor_sync(0xffffffff, m0,  off);
        m1  += __shfl_xor_sync(0xffffffff, m1,  off);
    }
    if (lane == 0) {
        float r = 1.f / (den + 1e-16f);
        out[d * 2]     = fmaxf(out[d * 2]     + m0 * r, 0.f);
        out[d * 2 + 1] = fmaxf(out[d * 2 + 1] + m1 * r, 0.f);
    }
}

// ---------------- launch ----------------
extern "C" void kernel_launch(void* const* d_in, const int* in_sizes, int n_in,
                              void* d_out, int out_size) {
    const float* x         = (const float*)d_in[0];
    const int*   ei        = (const int*)d_in[1];
    const float* bn1_g     = (const float*)d_in[2];
    const float* bn1_b     = (const float*)d_in[3];
    const float* lin1_W    = (const float*)d_in[4];
    const float* lin1_b    = (const float*)d_in[5];
    const float* con1_W    = (const float*)d_in[6];
    const float* con1_asrc = (const float*)d_in[7];
    const float* con1_adst = (const float*)d_in[8];
    const float* con1_b    = (const float*)d_in[9];
    const float* bn3_g     = (const float*)d_in[10];
    const float* bn3_b     = (const float*)d_in[11];
    const float* lin3_W    = (const float*)d_in[12];
    const float* lin3_b    = (const float*)d_in[13];
    const float* con3_W    = (const float*)d_in[14];
    const float* con3_asrc = (const float*)d_in[15];
    const float* con3_adst = (const float*)d_in[16];
    const float* con3_b    = (const float*)d_in[17];
    float* out = (float*)d_out;

    const int NCHUNK = (NN + 1 + 1023) / 1024;   // 49
    const int GSMEM = 2 * STAGEB;                // 81920 bytes

    cudaFuncSetAttribute(gemm_bf16, cudaFuncAttributeMaxDynamicSharedMemorySize, GSMEM);

    // Launches 1-3: BN1 stats/finalize, then fused prep (bnconv + wtconv + rowptr zero)
    bn_stats<<<BNPART, 256>>>(x, 0);
    bn_finalize<<<1, 256>>>(bn1_g, bn1_b);
    prep_k<<<PREP_A + PREP_W + PREP_Z, 256>>>(x, lin1_W, con1_W);

    // Launch 4 (ncu-profiled slot): the dual GEMM
    gemm_bf16<<<dim3((NN + 127) / 128, 4), 256, GSMEM>>>(lin1_b, con1_b);

    // CSR build
    hist_k<<<(EE + 255) / 256, 256>>>(ei);
    scan1_k<<<NCHUNK, 1024>>>();
    scan2_k<<<1, 64>>>(NCHUNK);
    scan3_k<<<NCHUNK - 1, 1024>>>();
    cursor_k<<<(NN + 255) / 256, 256>>>();
    scatter_k<<<(EE + 255) / 256, 256>>>(ei);

    // GAT1: logits then fused softmax+aggregate
    compute_al<<<(NN + 7) / 8, 256>>>(con1_asrc, con1_adst);
    gat1_fused<<<NN, 256>>>();

    // BN3 stats (relu fused into read)
    bn_stats<<<BNPART, 256>>>(nullptr, 1);
    bn_finalize<<<1, 256>>>(bn3_g, bn3_b);

    // layer 2
    layer2_row<<<(NN + 7) / 8, 256>>>(lin3_W, lin3_b, con3_W, con3_asrc, con3_adst, con3_b, out);
    gat_l2<<<(NN + 7) / 8, 256>>>(out);
}

// round 9
// speedup vs baseline: 3.7408x; 1.1924x over previous
#include <cuda_runtime.h>
#include <cuda_bf16.h>
#include <cstdint>

#define NN 50000
#define EE 800000
#define FDIM 256
#define HEADS 4
#define HID 64
#define BNPART 256

// ---------------- scratch (static device globals; allocation-free) ----------------
__device__ float  d_y1[NN * FDIM];     // linear1 output + GAT1 aggregation -> x1
__device__ float  d_h1[NN * FDIM];     // GAT1 transformed features
__device__ __nv_bfloat16 d_a_hi[NN * FDIM];   // BN(x) in bf16 hi
__device__ __nv_bfloat16 d_a_lo[NN * FDIM];   // residual lo
__device__ __nv_bfloat16 d_w_hi[2 * FDIM * FDIM];  // [mat][n][k] transposed weights
__device__ __nv_bfloat16 d_w_lo[2 * FDIM * FDIM];
__device__ float4 d_als1[NN];
__device__ float4 d_ald1[NN];
__device__ float4 d_p3[NN];            // packed layer-2: (als3, h0, h1, ald3)
__device__ float  d_bnps[BNPART * FDIM];
__device__ float  d_bnpq[BNPART * FDIM];
__device__ float  d_scale[FDIM];
__device__ float  d_shift[FDIM];
__device__ int d_rowptr[NN + 1];
__device__ int d_cursor[NN];
__device__ int d_csr_src[EE];
__device__ int d_chunksum[64];

__device__ __forceinline__ float lrelu(float x) { return x > 0.f ? x : 0.2f * x; }

// ---------------- BN stats: per-block partials (no atomics, no pre-zero) ----------------
__global__ void bn_stats(const float* __restrict__ x, int dorelu) {
    const float* src = x ? x : (const float*)d_y1;
    int c = threadIdx.x;
    float s = 0.f, s2 = 0.f;
    for (int r = blockIdx.x; r < NN; r += BNPART) {
        float v = src[r * FDIM + c];
        if (dorelu) v = fmaxf(v, 0.f);
        s += v; s2 += v * v;
    }
    d_bnps[blockIdx.x * FDIM + c] = s;
    d_bnpq[blockIdx.x * FDIM + c] = s2;
}
__global__ void bn_finalize(const float* __restrict__ g, const float* __restrict__ b) {
    int c = threadIdx.x;
    float s = 0.f, q = 0.f;
    #pragma unroll 8
    for (int i = 0; i < BNPART; i++) {
        s += d_bnps[i * FDIM + c];
        q += d_bnpq[i * FDIM + c];
    }
    const float invn = 1.0f / (float)NN;
    float mu = s * invn;
    float var = q * invn - mu * mu;
    float rs = rsqrtf(var + 1e-5f);
    float sc = rs * g[c];
    d_scale[c] = sc;
    d_shift[c] = b[c] - mu * sc;
}

// ---------------- prep: BN+hi/lo conv of A, weight transpose+conv, rowptr zero ----------------
#define PREP_A 12500
#define PREP_W 512
#define PREP_Z 196
__global__ void prep_k(const float* __restrict__ x,
                       const float* __restrict__ W0, const float* __restrict__ W1) {
    int bid = blockIdx.x;
    int t = threadIdx.x;
    if (bid < PREP_A) {
        int i = bid * 256 + t;
        int c = (i & 63) << 2;
        float4 v = ((const float4*)x)[i];
        float4 sc = *(const float4*)&d_scale[c];
        float4 sh = *(const float4*)&d_shift[c];
        float a0 = v.x * sc.x + sh.x, a1 = v.y * sc.y + sh.y;
        float a2 = v.z * sc.z + sh.z, a3 = v.w * sc.w + sh.w;
        __nv_bfloat16 h0 = __float2bfloat16_rn(a0), h1 = __float2bfloat16_rn(a1);
        __nv_bfloat16 h2 = __float2bfloat16_rn(a2), h3 = __float2bfloat16_rn(a3);
        __nv_bfloat162* ph = (__nv_bfloat162*)d_a_hi;
        ph[i * 2]     = __nv_bfloat162(h0, h1);
        ph[i * 2 + 1] = __nv_bfloat162(h2, h3);
        __nv_bfloat162* pl = (__nv_bfloat162*)d_a_lo;
        pl[i * 2]     = __nv_bfloat162(__float2bfloat16_rn(a0 - __bfloat162float(h0)),
                                       __float2bfloat16_rn(a1 - __bfloat162float(h1)));
        pl[i * 2 + 1] = __nv_bfloat162(__float2bfloat16_rn(a2 - __bfloat162float(h2)),
                                       __float2bfloat16_rn(a3 - __bfloat162float(h3)));
    } else if (bid < PREP_A + PREP_W) {
        int i = (bid - PREP_A) * 256 + t;
        int mat = i >> 16, r = i & 65535;
        int n = r >> 8, k = r & 255;
        const float* W = mat ? W1 : W0;
        float v = W[k * 256 + n];
        __nv_bfloat16 h = __float2bfloat16_rn(v);
        d_w_hi[i] = h;
        d_w_lo[i] = __float2bfloat16_rn(v - __bfloat162float(h));
    } else {
        int i = (bid - PREP_A - PREP_W) * 256 + t;
        if (i <= NN) d_rowptr[i] = 0;
    }
}

// ---------------- CSR build ----------------
__global__ void hist_k(const int* __restrict__ ei) {
    int e = blockIdx.x * blockDim.x + threadIdx.x;
    if (e < EE) atomicAdd(&d_rowptr[ei[EE + e] + 1], 1);
}
__global__ void scan1_k() {
    __shared__ int s[1024];
    int tid = threadIdx.x;
    int i = blockIdx.x * 1024 + tid;
    int v = (i <= NN) ? d_rowptr[i] : 0;
    s[tid] = v;
    __syncthreads();
    #pragma unroll
    for (int off = 1; off < 1024; off <<= 1) {
        int add = (tid >= off) ? s[tid - off] : 0;
        __syncthreads();
        s[tid] += add;
        __syncthreads();
    }
    if (i <= NN) d_rowptr[i] = s[tid];
    if (tid == 1023) d_chunksum[blockIdx.x] = s[1023];
}
__global__ void scan2_k(int nchunks) {
    __shared__ int s[64];
    int tid = threadIdx.x;
    int v = (tid < nchunks) ? d_chunksum[tid] : 0;
    s[tid] = v;
    __syncthreads();
    #pragma unroll
    for (int off = 1; off < 64; off <<= 1) {
        int add = (tid >= off) ? s[tid - off] : 0;
        __syncthreads();
        s[tid] += add;
        __syncthreads();
    }
    d_chunksum[tid] = s[tid];
}
__global__ void scan3_k() {
    int chunk = blockIdx.x + 1;
    int i = chunk * 1024 + threadIdx.x;
    if (i <= NN) d_rowptr[i] += d_chunksum[chunk - 1];
}
__global__ void cursor_k() {
    int i = blockIdx.x * blockDim.x + threadIdx.x;
    if (i < NN) d_cursor[i] = d_rowptr[i];
}
__global__ void scatter_k(const int* __restrict__ ei) {
    int e = blockIdx.x * blockDim.x + threadIdx.x;
    if (e >= EE) return;
    int s = ei[e], t = ei[EE + e];
    int pos = atomicAdd(&d_cursor[t], 1);
    d_csr_src[pos] = s;
}

// ---------------- bf16 split tensor-core GEMM (cp.async double-buffered) ----------------
#define SLDA 40
#define APLANE (128 * SLDA * 2)
#define ABUF (2 * APLANE)
#define STAGEB (2 * ABUF)

__device__ __forceinline__ void mma16816(float* d, const uint32_t* a, uint32_t b0, uint32_t b1) {
    asm volatile("mma.sync.aligned.m16n8k16.row.col.f32.bf16.bf16.f32 "
                 "{%0,%1,%2,%3}, {%4,%5,%6,%7}, {%8,%9}, {%0,%1,%2,%3};"
                 : "+f"(d[0]), "+f"(d[1]), "+f"(d[2]), "+f"(d[3])
                 : "r"(a[0]), "r"(a[1]), "r"(a[2]), "r"(a[3]), "r"(b0), "r"(b1));
}
__device__ __forceinline__ void ldsm4(uint32_t* r, uint32_t addr) {
    asm volatile("ldmatrix.sync.aligned.m8n8.x4.shared.b16 {%0,%1,%2,%3}, [%4];"
                 : "=r"(r[0]), "=r"(r[1]), "=r"(r[2]), "=r"(r[3]) : "r"(addr));
}
__device__ __forceinline__ void cpa16(uint32_t saddr, const void* gaddr, int bytes) {
    asm volatile("cp.async.cg.shared.global [%0], [%1], 16, %2;"
                 :: "r"(saddr), "l"(gaddr), "r"(bytes));
}

extern __shared__ char dynsmem[];

__global__ void __launch_bounds__(256, 2)
gemm_bf16(const float* __restrict__ b0a, const float* __restrict__ b0b) {
    int t = threadIdx.x;
    int m0 = blockIdx.x * 128;
    int mat = blockIdx.y >> 1;
    int n0 = (blockIdx.y & 1) * 128;
    const __nv_bfloat16* Bh = d_w_hi + mat * 65536;
    const __nv_bfloat16* Bl = d_w_lo + mat * 65536;
    float* C = mat ? d_h1 : d_y1;

    int lrow = t >> 1, seg = t & 1;
    int gm = m0 + lrow;
    bool aok = gm < NN;
    int gmc = aok ? gm : 0;
    int abytes = aok ? 16 : 0;

    const char* gAh = (const char*)(d_a_hi + (size_t)gmc * 256) + seg * 32;
    const char* gAl = (const char*)(d_a_lo + (size_t)gmc * 256) + seg * 32;
    const char* gBh = (const char*)(Bh + (size_t)(n0 + lrow) * 256) + seg * 32;
    const char* gBl = (const char*)(Bl + (size_t)(n0 + lrow) * 256) + seg * 32;

    uint32_t smem0 = (uint32_t)__cvta_generic_to_shared(dynsmem);
    uint32_t rowoff = (uint32_t)(lrow * (SLDA * 2) + seg * 32);

    auto issue = [&](int slab, int st) {
        uint32_t base = smem0 + st * STAGEB;
        int go = slab * 64;
        uint32_t sa = base + rowoff;
        cpa16(sa,               gAh + go,      abytes);
        cpa16(sa + 16,          gAh + go + 16, abytes);
        cpa16(sa + APLANE,      gAl + go,      abytes);
        cpa16(sa + APLANE + 16, gAl + go + 16, abytes);
        uint32_t sbb = base + ABUF + rowoff;
        cpa16(sbb,               gBh + go,      16);
        cpa16(sbb + 16,          gBh + go + 16, 16);
        cpa16(sbb + APLANE,      gBl + go,      16);
        cpa16(sbb + APLANE + 16, gBl + go + 16, 16);
        asm volatile("cp.async.commit_group;");
    };

    issue(0, 0);
    issue(1, 1);

    int wid = t >> 5, lane = t & 31;
    int wm0 = (wid & 1) * 64, wn0 = (wid >> 1) * 32;
    float acc[4][4][4] = {};

    int a_r = (lane & 15);
    int a_c = (lane >> 4) << 3;
    int b_r = (lane & 7) + ((lane & 16) ? 8 : 0);
    int b_c = (lane & 8) ? 8 : 0;

    for (int s = 0; s < 8; s++) {
        if (s < 7) asm volatile("cp.async.wait_group 1;");
        else       asm volatile("cp.async.wait_group 0;");
        __syncthreads();
        uint32_t sAu = smem0 + (s & 1) * STAGEB;
        uint32_t sBu = sAu + ABUF;
        // preload ALL B fragments for this stage (both kk halves) up front
        uint32_t bh[2][2][4], bl[2][2][4];
        #pragma unroll
        for (int kx = 0; kx < 2; kx++)
            #pragma unroll
            for (int jp = 0; jp < 2; jp++) {
                uint32_t addr = sBu + (uint32_t)(((wn0 + jp * 16 + b_r) * SLDA + kx * 16 + b_c) * 2);
                ldsm4(bh[kx][jp], addr);
                ldsm4(bl[kx][jp], addr + APLANE);
            }
        #pragma unroll
        for (int kx = 0; kx < 2; kx++) {
            int kk = kx * 16;
            #pragma unroll
            for (int i = 0; i < 4; i++) {
                uint32_t ah[4], al[4];
                uint32_t addr = sAu + (uint32_t)(((wm0 + i * 16 + a_r) * SLDA + kk + a_c) * 2);
                ldsm4(ah, addr);
                ldsm4(al, addr + APLANE);
                #pragma unroll
                for (int j = 0; j < 4; j++) {
                    int jp = j >> 1, o = (j & 1) * 2;
                    mma16816(acc[i][j], ah, bh[kx][jp][o], bh[kx][jp][o + 1]);
                    mma16816(acc[i][j], ah, bl[kx][jp][o], bl[kx][jp][o + 1]);
                    mma16816(acc[i][j], al, bh[kx][jp][o], bh[kx][jp][o + 1]);
                }
            }
        }
        __syncthreads();
        if (s + 2 < 8) issue(s + 2, s & 1);
    }

    int g = lane >> 2, tq = lane & 3;
    #pragma unroll
    for (int j = 0; j < 4; j++) {
        int gcol = n0 + wn0 + j * 8 + tq * 2;
        float bx = 0.f, by = 0.f;
        if (!mat) {
            bx = b0a[gcol] + b0b[gcol];
            by = b0a[gcol + 1] + b0b[gcol + 1];
        }
        #pragma unroll
        for (int i = 0; i < 4; i++) {
            int r0 = m0 + wm0 + i * 16 + g;
            if (r0 < NN)
                *(float2*)&C[(size_t)r0 * 256 + gcol] =
                    make_float2(acc[i][j][0] + bx, acc[i][j][1] + by);
            int r1 = r0 + 8;
            if (r1 < NN)
                *(float2*)&C[(size_t)r1 * 256 + gcol] =
                    make_float2(acc[i][j][2] + bx, acc[i][j][3] + by);
        }
    }
}

// ---------------- attention logit contributions (layer 1) ----------------
__global__ void compute_al(const float* __restrict__ asrc, const float* __restrict__ adst) {
    int warp = (blockIdx.x * blockDim.x + threadIdx.x) >> 5;
    int lane = threadIdx.x & 31;
    if (warp >= NN) return;
    const float4* hr = (const float4*)&d_h1[(size_t)warp * 256];
    int head = lane >> 3;
    float s = 0.f, d = 0.f;
    #pragma unroll
    for (int q = 0; q < 2; q++) {
        float4 hv = hr[lane * 2 + q];
        int cbase = (lane * 8 + q * 4) & 63;
        const float* as = asrc + head * 64 + cbase;
        const float* ad = adst + head * 64 + cbase;
        s += hv.x * as[0] + hv.y * as[1] + hv.z * as[2] + hv.w * as[3];
        d += hv.x * ad[0] + hv.y * ad[1] + hv.z * ad[2] + hv.w * ad[3];
    }
    #pragma unroll
    for (int off = 4; off > 0; off >>= 1) {
        s += __shfl_down_sync(0xffffffff, s, off);
        d += __shfl_down_sync(0xffffffff, d, off);
    }
    if ((lane & 7) == 0) {
        ((float*)&d_als1[warp])[head] = s;
        ((float*)&d_ald1[warp])[head] = d;
    }
}

// ---------------- layer-1 GAT: warp/dst, shfl-broadcast, no smem, no barriers ----------------
__global__ void gat1_warp() {
    int d = (blockIdx.x * blockDim.x + threadIdx.x) >> 5;
    int lane = threadIdx.x & 31;
    if (d >= NN) return;
    int b = d_rowptr[d], e = d_rowptr[d + 1];
    if (b == e) return;
    float4 ald = d_ald1[d];
    int h = lane >> 3;                 // head of my 8 channels
    int coff = lane * 8;               // my channel offset
    float4 acc0 = make_float4(0.f, 0.f, 0.f, 0.f);
    float4 acc1 = make_float4(0.f, 0.f, 0.f, 0.f);
    float den = 0.f;                   // my head's denominator (same across my 8-lane group)
    const float* __restrict__ hp = (const float*)d_h1;

    for (int c0 = b; c0 < e; c0 += 32) {
        int cnt = min(32, e - c0);
        int src = 0;
        float4 ex = make_float4(0.f, 0.f, 0.f, 0.f);
        if (lane < cnt) {
            src = d_csr_src[c0 + lane];
            float4 a = d_als1[src];
            ex.x = __expf(lrelu(a.x + ald.x));
            ex.y = __expf(lrelu(a.y + ald.y));
            ex.z = __expf(lrelu(a.z + ald.z));
            ex.w = __expf(lrelu(a.w + ald.w));
        }
        #pragma unroll 4
        for (int j = 0; j < cnt; j++) {
            int   sj = __shfl_sync(0xffffffffu, src,  j);
            float e0 = __shfl_sync(0xffffffffu, ex.x, j);
            float e1 = __shfl_sync(0xffffffffu, ex.y, j);
            float e2 = __shfl_sync(0xffffffffu, ex.z, j);
            float e3 = __shfl_sync(0xffffffffu, ex.w, j);
            float w = (h == 0) ? e0 : (h == 1) ? e1 : (h == 2) ? e2 : e3;
            den += w;
            const float4* hv = (const float4*)&hp[(size_t)sj * 256 + coff];
            float4 v0 = hv[0], v1 = hv[1];
            acc0.x += w * v0.x; acc0.y += w * v0.y;
            acc0.z += w * v0.z; acc0.w += w * v0.w;
            acc1.x += w * v1.x; acc1.y += w * v1.y;
            acc1.z += w * v1.z; acc1.w += w * v1.w;
        }
    }
    float r = 1.f / (den + 1e-16f);
    float4* yp = (float4*)&d_y1[(size_t)d * 256 + coff];
    float4 o0 = yp[0], o1 = yp[1];
    o0.x += acc0.x * r; o0.y += acc0.y * r; o0.z += acc0.z * r; o0.w += acc0.w * r;
    o1.x += acc1.x * r; o1.y += acc1.y * r; o1.z += acc1.z * r; o1.w += acc1.w * r;
    yp[0] = o0; yp[1] = o1;
}

// ---------------- layer 2: fused relu+BN + linear3 + GAT2 features/logits ----------------
__global__ void layer2_row(const float* __restrict__ lin3W, const float* __restrict__ lin3b,
                           const float* __restrict__ con3W, const float* __restrict__ asrc,
                           const float* __restrict__ adst, const float* __restrict__ con3b,
                           float* __restrict__ out) {
    int warp = (blockIdx.x * blockDim.x + threadIdx.x) >> 5;
    int lane = threadIdx.x & 31;
    if (warp >= NN) return;
    const float* row = (const float*)d_y1 + (size_t)warp * 256;
    float y0 = 0.f, y1v = 0.f, h0 = 0.f, h1v = 0.f;
    #pragma unroll
    for (int q = 0; q < 8; q++) {
        int c = lane + q * 32;
        float v = fmaxf(row[c], 0.f) * d_scale[c] + d_shift[c];
        y0  += v * lin3W[c * 2];
        y1v += v * lin3W[c * 2 + 1];
        h0  += v * con3W[c * 2];
        h1v += v * con3W[c * 2 + 1];
    }
    #pragma unroll
    for (int off = 16; off > 0; off >>= 1) {
        y0  += __shfl_xor_sync(0xffffffff, y0,  off);
        y1v += __shfl_xor_sync(0xffffffff, y1v, off);
        h0  += __shfl_xor_sync(0xffffffff, h0,  off);
        h1v += __shfl_xor_sync(0xffffffff, h1v, off);
    }
    if (lane == 0) {
        out[warp * 2]     = y0  + lin3b[0] + con3b[0];
        out[warp * 2 + 1] = y1v + lin3b[1] + con3b[1];
        d_p3[warp] = make_float4(h0 * asrc[0] + h1v * asrc[1],   // als3
                                 h0, h1v,                         // message features
                                 h0 * adst[0] + h1v * adst[1]);   // ald3
    }
}

// ---------------- layer-2 GAT + final relu (warp/dst, single LDG.128 per edge) ----------------
__global__ void gat_l2(float* __restrict__ out) {
    int d = (blockIdx.x * blockDim.x + threadIdx.x) >> 5;
    int lane = threadIdx.x & 31;
    if (d >= NN) return;
    int b = d_rowptr[d], e = d_rowptr[d + 1];
    float ald = d_p3[d].w;
    float den = 0.f, m0 = 0.f, m1 = 0.f;
    for (int j = b + lane; j < e; j += 32) {
        int src = d_csr_src[j];
        float4 p = d_p3[src];
        float ex = __expf(lrelu(p.x + ald));
        den += ex; m0 += ex * p.y; m1 += ex * p.z;
    }
    #pragma unroll
    for (int off = 16; off > 0; off >>= 1) {
        den += __shfl_xor_sync(0xffffffff, den, off);
        m0  += __shfl_xor_sync(0xffffffff, m0,  off);
        m1  += __shfl_xor_sync(0xffffffff, m1,  off);
    }
    if (lane == 0) {
        float r = 1.f / (den + 1e-16f);
        out[d * 2]     = fmaxf(out[d * 2]     + m0 * r, 0.f);
        out[d * 2 + 1] = fmaxf(out[d * 2 + 1] + m1 * r, 0.f);
    }
}

// ---------------- launch ----------------
extern "C" void kernel_launch(void* const* d_in, const int* in_sizes, int n_in,
                              void* d_out, int out_size) {
    const float* x         = (const float*)d_in[0];
    const int*   ei        = (const int*)d_in[1];
    const float* bn1_g     = (const float*)d_in[2];
    const float* bn1_b     = (const float*)d_in[3];
    const float* lin1_W    = (const float*)d_in[4];
    const float* lin1_b    = (const float*)d_in[5];
    const float* con1_W    = (const float*)d_in[6];
    const float* con1_asrc = (const float*)d_in[7];
    const float* con1_adst = (const float*)d_in[8];
    const float* con1_b    = (const float*)d_in[9];
    const float* bn3_g     = (const float*)d_in[10];
    const float* bn3_b     = (const float*)d_in[11];
    const float* lin3_W    = (const float*)d_in[12];
    const float* lin3_b    = (const float*)d_in[13];
    const float* con3_W    = (const float*)d_in[14];
    const float* con3_asrc = (const float*)d_in[15];
    const float* con3_adst = (const float*)d_in[16];
    const float* con3_b    = (const float*)d_in[17];
    float* out = (float*)d_out;

    const int NCHUNK = (NN + 1 + 1023) / 1024;   // 49
    const int GSMEM = 2 * STAGEB;                // 81920 bytes

    cudaFuncSetAttribute(gemm_bf16, cudaFuncAttributeMaxDynamicSharedMemorySize, GSMEM);

    // Launches 1-3: BN1 stats/finalize, fused prep
    bn_stats<<<BNPART, 256>>>(x, 0);
    bn_finalize<<<1, 256>>>(bn1_g, bn1_b);
    prep_k<<<PREP_A + PREP_W + PREP_Z, 256>>>(x, lin1_W, con1_W);

    // Launch 4 (ncu-profiled slot): the dual GEMM
    gemm_bf16<<<dim3((NN + 127) / 128, 4), 256, GSMEM>>>(lin1_b, con1_b);

    // CSR build
    hist_k<<<(EE + 255) / 256, 256>>>(ei);
    scan1_k<<<NCHUNK, 1024>>>();
    scan2_k<<<1, 64>>>(NCHUNK);
    scan3_k<<<NCHUNK - 1, 1024>>>();
    cursor_k<<<(NN + 255) / 256, 256>>>();
    scatter_k<<<(EE + 255) / 256, 256>>>(ei);

    // GAT1: logits then warp-per-dst fused softmax+aggregate
    compute_al<<<(NN + 7) / 8, 256>>>(con1_asrc, con1_adst);
    gat1_warp<<<(NN + 7) / 8, 256>>>();

    // BN3 stats (relu fused into read)
    bn_stats<<<BNPART, 256>>>(nullptr, 1);
    bn_finalize<<<1, 256>>>(bn3_g, bn3_b);

    // layer 2
    layer2_row<<<(NN + 7) / 8, 256>>>(lin3_W, lin3_b, con3_W, con3_asrc, con3_adst, con3_b, out);
    gat_l2<<<(NN + 7) / 8, 256>>>(out);
}

// round 10
// speedup vs baseline: 3.7580x; 1.0046x over previous
#include <cuda_runtime.h>
#include <cuda_bf16.h>
#include <cstdint>

#define NN 50000
#define EE 800000
#define FDIM 256
#define HEADS 4
#define HID 64
#define BNPART 256

// ---------------- scratch (static device globals; allocation-free) ----------------
__device__ float  d_y1[NN * FDIM];     // linear1 output + GAT1 aggregation -> x1
__device__ float  d_h1[NN * FDIM];     // GAT1 transformed features
__device__ __nv_bfloat16 d_a_hi[NN * FDIM];   // BN(x) in bf16 hi
__device__ __nv_bfloat16 d_a_lo[NN * FDIM];   // residual lo
__device__ __nv_bfloat16 d_w_hi[2 * FDIM * FDIM];  // [mat][n][k] transposed weights
__device__ __nv_bfloat16 d_w_lo[2 * FDIM * FDIM];
__device__ float4 d_als1[NN];
__device__ float4 d_ald1[NN];
__device__ float4 d_p3[NN];            // packed layer-2: (als3, h0, h1, ald3)
__device__ float  d_bnps[BNPART * FDIM];
__device__ float  d_bnpq[BNPART * FDIM];
__device__ float  d_scale[FDIM];
__device__ float  d_shift[FDIM];
__device__ int d_rowptr[NN + 1];
__device__ int d_cursor[NN];
__device__ int d_csr_src[EE];
__device__ int d_chunksum[64];

__device__ __forceinline__ float lrelu(float x) { return x > 0.f ? x : 0.2f * x; }

// ---------------- BN stats: per-block partials (no atomics, no pre-zero) ----------------
__global__ void bn_stats(const float* __restrict__ x, int dorelu) {
    const float* src = x ? x : (const float*)d_y1;
    int c = threadIdx.x;
    float s = 0.f, s2 = 0.f;
    for (int r = blockIdx.x; r < NN; r += BNPART) {
        float v = src[r * FDIM + c];
        if (dorelu) v = fmaxf(v, 0.f);
        s += v; s2 += v * v;
    }
    d_bnps[blockIdx.x * FDIM + c] = s;
    d_bnpq[blockIdx.x * FDIM + c] = s2;
}
__global__ void bn_finalize(const float* __restrict__ g, const float* __restrict__ b) {
    int c = threadIdx.x;
    float s = 0.f, q = 0.f;
    #pragma unroll 8
    for (int i = 0; i < BNPART; i++) {
        s += d_bnps[i * FDIM + c];
        q += d_bnpq[i * FDIM + c];
    }
    const float invn = 1.0f / (float)NN;
    float mu = s * invn;
    float var = q * invn - mu * mu;
    float rs = rsqrtf(var + 1e-5f);
    float sc = rs * g[c];
    d_scale[c] = sc;
    d_shift[c] = b[c] - mu * sc;
}

// ---------------- prep: BN+hi/lo conv of A, weight transpose+conv, rowptr zero ----------------
#define PREP_A 12500
#define PREP_W 512
#define PREP_Z 196
__global__ void prep_k(const float* __restrict__ x,
                       const float* __restrict__ W0, const float* __restrict__ W1) {
    int bid = blockIdx.x;
    int t = threadIdx.x;
    if (bid < PREP_A) {
        int i = bid * 256 + t;
        int c = (i & 63) << 2;
        float4 v = ((const float4*)x)[i];
        float4 sc = *(const float4*)&d_scale[c];
        float4 sh = *(const float4*)&d_shift[c];
        float a0 = v.x * sc.x + sh.x, a1 = v.y * sc.y + sh.y;
        float a2 = v.z * sc.z + sh.z, a3 = v.w * sc.w + sh.w;
        __nv_bfloat16 h0 = __float2bfloat16_rn(a0), h1 = __float2bfloat16_rn(a1);
        __nv_bfloat16 h2 = __float2bfloat16_rn(a2), h3 = __float2bfloat16_rn(a3);
        __nv_bfloat162* ph = (__nv_bfloat162*)d_a_hi;
        ph[i * 2]     = __nv_bfloat162(h0, h1);
        ph[i * 2 + 1] = __nv_bfloat162(h2, h3);
        __nv_bfloat162* pl = (__nv_bfloat162*)d_a_lo;
        pl[i * 2]     = __nv_bfloat162(__float2bfloat16_rn(a0 - __bfloat162float(h0)),
                                       __float2bfloat16_rn(a1 - __bfloat162float(h1)));
        pl[i * 2 + 1] = __nv_bfloat162(__float2bfloat16_rn(a2 - __bfloat162float(h2)),
                                       __float2bfloat16_rn(a3 - __bfloat162float(h3)));
    } else if (bid < PREP_A + PREP_W) {
        int i = (bid - PREP_A) * 256 + t;
        int mat = i >> 16, r = i & 65535;
        int n = r >> 8, k = r & 255;
        const float* W = mat ? W1 : W0;
        float v = W[k * 256 + n];
        __nv_bfloat16 h = __float2bfloat16_rn(v);
        d_w_hi[i] = h;
        d_w_lo[i] = __float2bfloat16_rn(v - __bfloat162float(h));
    } else {
        int i = (bid - PREP_A - PREP_W) * 256 + t;
        if (i <= NN) d_rowptr[i] = 0;
    }
}

// ---------------- CSR build ----------------
__global__ void hist_k(const int* __restrict__ ei) {
    int e = blockIdx.x * blockDim.x + threadIdx.x;
    if (e < EE) atomicAdd(&d_rowptr[ei[EE + e] + 1], 1);
}
__global__ void scan1_k() {
    __shared__ int s[1024];
    int tid = threadIdx.x;
    int i = blockIdx.x * 1024 + tid;
    int v = (i <= NN) ? d_rowptr[i] : 0;
    s[tid] = v;
    __syncthreads();
    #pragma unroll
    for (int off = 1; off < 1024; off <<= 1) {
        int add = (tid >= off) ? s[tid - off] : 0;
        __syncthreads();
        s[tid] += add;
        __syncthreads();
    }
    if (i <= NN) {
        d_rowptr[i] = s[tid];
        if (blockIdx.x == 0 && i < NN) d_cursor[i] = s[tid];  // chunk-0 values are final
    }
    if (tid == 1023) d_chunksum[blockIdx.x] = s[1023];
}
__global__ void scan2_k(int nchunks) {
    __shared__ int s[64];
    int tid = threadIdx.x;
    int v = (tid < nchunks) ? d_chunksum[tid] : 0;
    s[tid] = v;
    __syncthreads();
    #pragma unroll
    for (int off = 1; off < 64; off <<= 1) {
        int add = (tid >= off) ? s[tid - off] : 0;
        __syncthreads();
        s[tid] += add;
        __syncthreads();
    }
    d_chunksum[tid] = s[tid];
}
__global__ void scan3_k() {
    int chunk = blockIdx.x + 1;
    int i = chunk * 1024 + threadIdx.x;
    if (i <= NN) {
        int v = d_rowptr[i] + d_chunksum[chunk - 1];
        d_rowptr[i] = v;
        if (i < NN) d_cursor[i] = v;                          // fused cursor init
    }
}
__global__ void scatter_k(const int* __restrict__ ei) {
    int e = blockIdx.x * blockDim.x + threadIdx.x;
    if (e >= EE) return;
    int s = ei[e], t = ei[EE + e];
    int pos = atomicAdd(&d_cursor[t], 1);
    d_csr_src[pos] = s;
}

// ---------------- bf16 split tensor-core GEMM: 4-stage deep pipeline, BK=16 ----------------
#define SLDA 24                       // halves per row (48 B, LDSM conflict-free)
#define PLANE (128 * SLDA * 2)        // 6144 B per plane
#define STG (4 * PLANE)               // stage: Ah, Al, Bh, Bl = 24576 B
#define GSMEM (4 * STG)               // 98304 B

__device__ __forceinline__ void mma16816(float* d, const uint32_t* a, uint32_t b0, uint32_t b1) {
    asm volatile("mma.sync.aligned.m16n8k16.row.col.f32.bf16.bf16.f32 "
                 "{%0,%1,%2,%3}, {%4,%5,%6,%7}, {%8,%9}, {%0,%1,%2,%3};"
                 : "+f"(d[0]), "+f"(d[1]), "+f"(d[2]), "+f"(d[3])
                 : "r"(a[0]), "r"(a[1]), "r"(a[2]), "r"(a[3]), "r"(b0), "r"(b1));
}
__device__ __forceinline__ void ldsm4(uint32_t* r, uint32_t addr) {
    asm volatile("ldmatrix.sync.aligned.m8n8.x4.shared.b16 {%0,%1,%2,%3}, [%4];"
                 : "=r"(r[0]), "=r"(r[1]), "=r"(r[2]), "=r"(r[3]) : "r"(addr));
}
__device__ __forceinline__ void cpa16(uint32_t saddr, const void* gaddr, int bytes) {
    asm volatile("cp.async.cg.shared.global [%0], [%1], 16, %2;"
                 :: "r"(saddr), "l"(gaddr), "r"(bytes));
}

extern __shared__ char dynsmem[];

__global__ void __launch_bounds__(256, 2)
gemm_bf16(const float* __restrict__ b0a, const float* __restrict__ b0b) {
    int t = threadIdx.x;
    // grid: x = {mat,n-half} (fast — wave-adjacent CTAs share the A tile), y = m tile
    int mat = blockIdx.x >> 1;
    int n0 = (blockIdx.x & 1) * 128;
    int m0 = blockIdx.y * 128;
    const __nv_bfloat16* Bh = d_w_hi + mat * 65536;
    const __nv_bfloat16* Bl = d_w_lo + mat * 65536;
    float* C = mat ? d_h1 : d_y1;

    int lrow = t >> 1, seg = t & 1;
    int gm = m0 + lrow;
    bool aok = gm < NN;
    int gmc = aok ? gm : 0;
    int abytes = aok ? 16 : 0;

    const char* gAh = (const char*)(d_a_hi + (size_t)gmc * 256) + seg * 16;
    const char* gAl = (const char*)(d_a_lo + (size_t)gmc * 256) + seg * 16;
    const char* gBh = (const char*)(Bh + (size_t)(n0 + lrow) * 256) + seg * 16;
    const char* gBl = (const char*)(Bl + (size_t)(n0 + lrow) * 256) + seg * 16;

    uint32_t smem0 = (uint32_t)__cvta_generic_to_shared(dynsmem);
    uint32_t rowoff = (uint32_t)(lrow * 48 + seg * 16);

    // issue loads for k-slab `slab` (16 halves = 32 B per row) into stage buffer `buf`
    auto issue = [&](int slab, int buf) {
        uint32_t base = smem0 + buf * STG + rowoff;
        int go = slab * 32;
        cpa16(base,             gAh + go, abytes);
        cpa16(base + PLANE,     gAl + go, abytes);
        cpa16(base + 2 * PLANE, gBh + go, 16);
        cpa16(base + 3 * PLANE, gBl + go, 16);
        asm volatile("cp.async.commit_group;");
    };

    issue(0, 0);
    issue(1, 1);
    issue(2, 2);

    int wid = t >> 5, lane = t & 31;
    int wm0 = (wid & 1) * 64, wn0 = (wid >> 1) * 32;
    float acc[4][4][4] = {};

    int a_r = (lane & 15);
    int a_c = (lane >> 4) << 3;
    int b_r = (lane & 7) + ((lane & 16) ? 8 : 0);
    int b_c = (lane & 8) ? 8 : 0;

    for (int s = 0; s < 16; s++) {
        asm volatile("cp.async.wait_group 2;");
        __syncthreads();
        if (s + 3 < 16) issue(s + 3, (s + 3) & 3);
        else            asm volatile("cp.async.commit_group;");   // dummy: keep pending==3

        uint32_t sAu = smem0 + (s & 3) * STG;
        uint32_t sBu = sAu + 2 * PLANE;
        uint32_t bh[2][4], bl[2][4];
        #pragma unroll
        for (int jp = 0; jp < 2; jp++) {
            uint32_t addr = sBu + (uint32_t)(((wn0 + jp * 16 + b_r) * SLDA + b_c) * 2);
            ldsm4(bh[jp], addr);
            ldsm4(bl[jp], addr + PLANE);
        }
        #pragma unroll
        for (int i = 0; i < 4; i++) {
            uint32_t ah[4], al[4];
            uint32_t addr = sAu + (uint32_t)(((wm0 + i * 16 + a_r) * SLDA + a_c) * 2);
            ldsm4(ah, addr);
            ldsm4(al, addr + PLANE);
            #pragma unroll
            for (int j = 0; j < 4; j++) {
                int jp = j >> 1, o = (j & 1) * 2;
                mma16816(acc[i][j], ah, bh[jp][o], bh[jp][o + 1]);
                mma16816(acc[i][j], ah, bl[jp][o], bl[jp][o + 1]);
                mma16816(acc[i][j], al, bh[jp][o], bh[jp][o + 1]);
            }
        }
    }

    int g = lane >> 2, tq = lane & 3;
    #pragma unroll
    for (int j = 0; j < 4; j++) {
        int gcol = n0 + wn0 + j * 8 + tq * 2;
        float bx = 0.f, by = 0.f;
        if (!mat) {
            bx = b0a[gcol] + b0b[gcol];
            by = b0a[gcol + 1] + b0b[gcol + 1];
        }
        #pragma unroll
        for (int i = 0; i < 4; i++) {
            int r0 = m0 + wm0 + i * 16 + g;
            if (r0 < NN)
                *(float2*)&C[(size_t)r0 * 256 + gcol] =
                    make_float2(acc[i][j][0] + bx, acc[i][j][1] + by);
            int r1 = r0 + 8;
            if (r1 < NN)
                *(float2*)&C[(size_t)r1 * 256 + gcol] =
                    make_float2(acc[i][j][2] + bx, acc[i][j][3] + by);
        }
    }
}

// ---------------- attention logit contributions (layer 1) ----------------
__global__ void compute_al(const float* __restrict__ asrc, const float* __restrict__ adst) {
    int warp = (blockIdx.x * blockDim.x + threadIdx.x) >> 5;
    int lane = threadIdx.x & 31;
    if (warp >= NN) return;
    const float4* hr = (const float4*)&d_h1[(size_t)warp * 256];
    int head = lane >> 3;
    float s = 0.f, d = 0.f;
    #pragma unroll
    for (int q = 0; q < 2; q++) {
        float4 hv = hr[lane * 2 + q];
        int cbase = (lane * 8 + q * 4) & 63;
        const float* as = asrc + head * 64 + cbase;
        const float* ad = adst + head * 64 + cbase;
        s += hv.x * as[0] + hv.y * as[1] + hv.z * as[2] + hv.w * as[3];
        d += hv.x * ad[0] + hv.y * ad[1] + hv.z * ad[2] + hv.w * ad[3];
    }
    #pragma unroll
    for (int off = 4; off > 0; off >>= 1) {
        s += __shfl_down_sync(0xffffffff, s, off);
        d += __shfl_down_sync(0xffffffff, d, off);
    }
    if ((lane & 7) == 0) {
        ((float*)&d_als1[warp])[head] = s;
        ((float*)&d_ald1[warp])[head] = d;
    }
}

// ---------------- layer-1 GAT: warp/dst, shfl-broadcast, no smem, no barriers ----------------
__global__ void gat1_warp() {
    int d = (blockIdx.x * blockDim.x + threadIdx.x) >> 5;
    int lane = threadIdx.x & 31;
    if (d >= NN) return;
    int b = d_rowptr[d], e = d_rowptr[d + 1];
    if (b == e) return;
    float4 ald = d_ald1[d];
    int h = lane >> 3;
    int coff = lane * 8;
    float4 acc0 = make_float4(0.f, 0.f, 0.f, 0.f);
    float4 acc1 = make_float4(0.f, 0.f, 0.f, 0.f);
    float den = 0.f;
    const float* __restrict__ hp = (const float*)d_h1;

    for (int c0 = b; c0 < e; c0 += 32) {
        int cnt = min(32, e - c0);
        int src = 0;
        float4 ex = make_float4(0.f, 0.f, 0.f, 0.f);
        if (lane < cnt) {
            src = d_csr_src[c0 + lane];
            float4 a = d_als1[src];
            ex.x = __expf(lrelu(a.x + ald.x));
            ex.y = __expf(lrelu(a.y + ald.y));
            ex.z = __expf(lrelu(a.z + ald.z));
            ex.w = __expf(lrelu(a.w + ald.w));
        }
        #pragma unroll 4
        for (int j = 0; j < cnt; j++) {
            int   sj = __shfl_sync(0xffffffffu, src,  j);
            float e0 = __shfl_sync(0xffffffffu, ex.x, j);
            float e1 = __shfl_sync(0xffffffffu, ex.y, j);
            float e2 = __shfl_sync(0xffffffffu, ex.z, j);
            float e3 = __shfl_sync(0xffffffffu, ex.w, j);
            float w = (h == 0) ? e0 : (h == 1) ? e1 : (h == 2) ? e2 : e3;
            den += w;
            const float4* hv = (const float4*)&hp[(size_t)sj * 256 + coff];
            float4 v0 = hv[0], v1 = hv[1];
            acc0.x += w * v0.x; acc0.y += w * v0.y;
            acc0.z += w * v0.z; acc0.w += w * v0.w;
            acc1.x += w * v1.x; acc1.y += w * v1.y;
            acc1.z += w * v1.z; acc1.w += w * v1.w;
        }
    }
    float r = 1.f / (den + 1e-16f);
    float4* yp = (float4*)&d_y1[(size_t)d * 256 + coff];
    float4 o0 = yp[0], o1 = yp[1];
    o0.x += acc0.x * r; o0.y += acc0.y * r; o0.z += acc0.z * r; o0.w += acc0.w * r;
    o1.x += acc1.x * r; o1.y += acc1.y * r; o1.z += acc1.z * r; o1.w += acc1.w * r;
    yp[0] = o0; yp[1] = o1;
}

// ---------------- layer 2: fused relu+BN + linear3 + GAT2 features/logits ----------------
__global__ void layer2_row(const float* __restrict__ lin3W, const float* __restrict__ lin3b,
                           const float* __restrict__ con3W, const float* __restrict__ asrc,
                           const float* __restrict__ adst, const float* __restrict__ con3b,
                           float* __restrict__ out) {
    int warp = (blockIdx.x * blockDim.x + threadIdx.x) >> 5;
    int lane = threadIdx.x & 31;
    if (warp >= NN) return;
    const float* row = (const float*)d_y1 + (size_t)warp * 256;
    float y0 = 0.f, y1v = 0.f, h0 = 0.f, h1v = 0.f;
    #pragma unroll
    for (int q = 0; q < 8; q++) {
        int c = lane + q * 32;
        float v = fmaxf(row[c], 0.f) * d_scale[c] + d_shift[c];
        y0  += v * lin3W[c * 2];
        y1v += v * lin3W[c * 2 + 1];
        h0  += v * con3W[c * 2];
        h1v += v * con3W[c * 2 + 1];
    }
    #pragma unroll
    for (int off = 16; off > 0; off >>= 1) {
        y0  += __shfl_xor_sync(0xffffffff, y0,  off);
        y1v += __shfl_xor_sync(0xffffffff, y1v, off);
        h0  += __shfl_xor_sync(0xffffffff, h0,  off);
        h1v += __shfl_xor_sync(0xffffffff, h1v, off);
    }
    if (lane == 0) {
        out[warp * 2]     = y0  + lin3b[0] + con3b[0];
        out[warp * 2 + 1] = y1v + lin3b[1] + con3b[1];
        d_p3[warp] = make_float4(h0 * asrc[0] + h1v * asrc[1],
                                 h0, h1v,
                                 h0 * adst[0] + h1v * adst[1]);
    }
}

// ---------------- layer-2 GAT + final relu (warp/dst, single LDG.128 per edge) ----------------
__global__ void gat_l2(float* __restrict__ out) {
    int d = (blockIdx.x * blockDim.x + threadIdx.x) >> 5;
    int lane = threadIdx.x & 31;
    if (d >= NN) return;
    int b = d_rowptr[d], e = d_rowptr[d + 1];
    float ald = d_p3[d].w;
    float den = 0.f, m0 = 0.f, m1 = 0.f;
    for (int j = b + lane; j < e; j += 32) {
        int src = d_csr_src[j];
        float4 p = d_p3[src];
        float ex = __expf(lrelu(p.x + ald));
        den += ex; m0 += ex * p.y; m1 += ex * p.z;
    }
    #pragma unroll
    for (int off = 16; off > 0; off >>= 1) {
        den += __shfl_xor_sync(0xffffffff, den, off);
        m0  += __shfl_xor_sync(0xffffffff, m0,  off);
        m1  += __shfl_xor_sync(0xffffffff, m1,  off);
    }
    if (lane == 0) {
        float r = 1.f / (den + 1e-16f);
        out[d * 2]     = fmaxf(out[d * 2]     + m0 * r, 0.f);
        out[d * 2 + 1] = fmaxf(out[d * 2 + 1] + m1 * r, 0.f);
    }
}

// ---------------- launch ----------------
extern "C" void kernel_launch(void* const* d_in, const int* in_sizes, int n_in,
                              void* d_out, int out_size) {
    const float* x         = (const float*)d_in[0];
    const int*   ei        = (const int*)d_in[1];
    const float* bn1_g     = (const float*)d_in[2];
    const float* bn1_b     = (const float*)d_in[3];
    const float* lin1_W    = (const float*)d_in[4];
    const float* lin1_b    = (const float*)d_in[5];
    const float* con1_W    = (const float*)d_in[6];
    const float* con1_asrc = (const float*)d_in[7];
    const float* con1_adst = (const float*)d_in[8];
    const float* con1_b    = (const float*)d_in[9];
    const float* bn3_g     = (const float*)d_in[10];
    const float* bn3_b     = (const float*)d_in[11];
    const float* lin3_W    = (const float*)d_in[12];
    const float* lin3_b    = (const float*)d_in[13];
    const float* con3_W    = (const float*)d_in[14];
    const float* con3_asrc = (const float*)d_in[15];
    const float* con3_adst = (const float*)d_in[16];
    const float* con3_b    = (const float*)d_in[17];
    float* out = (float*)d_out;

    const int NCHUNK = (NN + 1 + 1023) / 1024;   // 49

    cudaFuncSetAttribute(gemm_bf16, cudaFuncAttributeMaxDynamicSharedMemorySize, GSMEM);

    // Launches 1-3: BN1 stats/finalize, fused prep
    bn_stats<<<BNPART, 256>>>(x, 0);
    bn_finalize<<<1, 256>>>(bn1_g, bn1_b);
    prep_k<<<PREP_A + PREP_W + PREP_Z, 256>>>(x, lin1_W, con1_W);

    // Launch 4 (ncu-profiled slot): the dual GEMM (4-stage pipeline)
    gemm_bf16<<<dim3(4, (NN + 127) / 128), 256, GSMEM>>>(lin1_b, con1_b);

    // CSR build (cursor init fused into scans)
    hist_k<<<(EE + 255) / 256, 256>>>(ei);
    scan1_k<<<NCHUNK, 1024>>>();
    scan2_k<<<1, 64>>>(NCHUNK);
    scan3_k<<<NCHUNK - 1, 1024>>>();
    scatter_k<<<(EE + 255) / 256, 256>>>(ei);

    // GAT1: logits then warp-per-dst fused softmax+aggregate
    compute_al<<<(NN + 7) / 8, 256>>>(con1_asrc, con1_adst);
    gat1_warp<<<(NN + 7) / 8, 256>>>();

    // BN3 stats (relu fused into read)
    bn_stats<<<BNPART, 256>>>(nullptr, 1);
    bn_finalize<<<1, 256>>>(bn3_g, bn3_b);

    // layer 2
    layer2_row<<<(NN + 7) / 8, 256>>>(lin3_W, lin3_b, con3_W, con3_asrc, con3_adst, con3_b, out);
    gat_l2<<<(NN + 7) / 8, 256>>>(out);
}